// round 4
// baseline (speedup 1.0000x reference)
#include <cuda_runtime.h>
#include <math.h>

// ---------------------------------------------------------------------------
// Problem constants (fixed by the dataset)
// ---------------------------------------------------------------------------
#define NN 50000      // nodes
#define NH 10000      // hyperedges
#define NE 250000     // incidences
#define DIM 512       // feature dim

// ---------------------------------------------------------------------------
// Scratch (static __device__ arrays; no allocation allowed)
// ---------------------------------------------------------------------------
__device__ float g_n0[(size_t)NN * DIM];
__device__ float g_n1[(size_t)NN * DIM];
__device__ float g_n2[(size_t)NN * DIM];
__device__ float g_h0[(size_t)NH * DIM];
__device__ float g_h1[(size_t)NH * DIM];
__device__ float g_h2[(size_t)NH * DIM];
__device__ float g_cntE[NH];
__device__ float g_cntV[NN];
__device__ int   g_minv;

// ---------------------------------------------------------------------------
// Small utility kernels
// ---------------------------------------------------------------------------
__global__ void k_init_min() { g_minv = 0x7fffffff; }

__global__ void k_min_reduce(const int* __restrict__ idx, int n) {
    int v = 0x7fffffff;
    for (int i = blockIdx.x * blockDim.x + threadIdx.x; i < n;
         i += gridDim.x * blockDim.x)
        v = min(v, __ldg(idx + i));
#pragma unroll
    for (int o = 16; o > 0; o >>= 1) v = min(v, __shfl_xor_sync(0xffffffffu, v, o));
    if ((threadIdx.x & 31) == 0) atomicMin(&g_minv, v);
}

__global__ void k_zero4(float4* __restrict__ p, size_t n4) {
    size_t i = (size_t)blockIdx.x * blockDim.x + threadIdx.x;
    size_t stride = (size_t)gridDim.x * blockDim.x;
    float4 z = make_float4(0.f, 0.f, 0.f, 0.f);
    for (; i < n4; i += stride) p[i] = z;
}

__global__ void k_hist(const int* __restrict__ idx, float* __restrict__ cnt,
                       int n, int shift) {
    int i = blockIdx.x * blockDim.x + threadIdx.x;
    if (i < n) {
        int s = __ldg(idx + i) - (shift ? g_minv : 0);
        atomicAdd(&cnt[s], 1.f);
    }
}

// ---------------------------------------------------------------------------
// LayerNorm over D=512, optional per-row prescale by 1/max(cnt,1)
// (absorbs the segment-mean division exactly)
// blockDim = 128, one block per row, float4 per thread
// ---------------------------------------------------------------------------
__global__ __launch_bounds__(128) void k_ln(
    const float* __restrict__ in, float* __restrict__ out,
    const float* __restrict__ w, const float* __restrict__ b,
    const float* __restrict__ cnt, int N)
{
    int row = blockIdx.x;
    if (row >= N) return;
    int t = threadIdx.x;

    float scale = 1.f;
    if (cnt) scale = 1.f / fmaxf(__ldg(cnt + row), 1.f);

    float4 v = reinterpret_cast<const float4*>(in + (size_t)row * DIM)[t];
    v.x *= scale; v.y *= scale; v.z *= scale; v.w *= scale;

    float s  = v.x + v.y + v.z + v.w;
    float ss = v.x * v.x + v.y * v.y + v.z * v.z + v.w * v.w;
#pragma unroll
    for (int o = 16; o > 0; o >>= 1) {
        s  += __shfl_xor_sync(0xffffffffu, s, o);
        ss += __shfl_xor_sync(0xffffffffu, ss, o);
    }
    __shared__ float sh_s[4], sh_ss[4];
    int wid = t >> 5;
    if ((t & 31) == 0) { sh_s[wid] = s; sh_ss[wid] = ss; }
    __syncthreads();
    s  = sh_s[0] + sh_s[1] + sh_s[2] + sh_s[3];
    ss = sh_ss[0] + sh_ss[1] + sh_ss[2] + sh_ss[3];

    float mu   = s * (1.f / DIM);
    float var  = ss * (1.f / DIM) - mu * mu;
    float rstd = rsqrtf(var + 1e-5f);

    float4 wv = reinterpret_cast<const float4*>(w)[t];
    float4 bv = reinterpret_cast<const float4*>(b)[t];
    float4 o;
    o.x = (v.x - mu) * rstd * wv.x + bv.x;
    o.y = (v.y - mu) * rstd * wv.y + bv.y;
    o.z = (v.z - mu) * rstd * wv.z + bv.z;
    o.w = (v.w - mu) * rstd * wv.w + bv.w;
    reinterpret_cast<float4*>(out + (size_t)row * DIM)[t] = o;
}

// ---------------------------------------------------------------------------
// FP32 SGEMM: C[M,512] = A[M,512] @ W[512,512] + bias (+ optional ReLU)
// 128x128 tiles, BK=16, 256 threads, 8x8 per thread, gmem prefetch
// ---------------------------------------------------------------------------
__global__ __launch_bounds__(256) void k_gemm(
    const float* __restrict__ A, const float* __restrict__ W,
    const float* __restrict__ bias, float* __restrict__ C,
    int M, int relu)
{
    constexpr int BM = 128, BN = 128, BK = 16;
    __shared__ float As[BK][BM + 4];
    __shared__ float Bs[BK][BN];

    const int t  = threadIdx.x;
    const int bm = blockIdx.y * BM;
    const int bn = blockIdx.x * BN;
    const int tx = t & 15;
    const int ty = t >> 4;

    // A-tile load mapping: rows ar, ar+64 ; k-offset ak..ak+3
    const int ar = t >> 2;
    const int ak = (t & 3) << 2;
    // B-tile load mapping: rows br, br+8 ; cols bc..bc+3
    const int br = t >> 5;
    const int bc = (t & 31) << 2;

    const int r0 = bm + ar, r1 = bm + ar + 64;

    float acc[8][8];
#pragma unroll
    for (int i = 0; i < 8; i++)
#pragma unroll
        for (int j = 0; j < 8; j++) acc[i][j] = 0.f;

    const float4 z4 = make_float4(0.f, 0.f, 0.f, 0.f);
    float4 a0 = z4, a1 = z4, b0, b1;

    // preload k0 = 0
    if (r0 < M) a0 = *reinterpret_cast<const float4*>(A + (size_t)r0 * DIM + ak);
    if (r1 < M) a1 = *reinterpret_cast<const float4*>(A + (size_t)r1 * DIM + ak);
    b0 = *reinterpret_cast<const float4*>(W + (size_t)br * DIM + bn + bc);
    b1 = *reinterpret_cast<const float4*>(W + (size_t)(br + 8) * DIM + bn + bc);

    for (int k0 = 0; k0 < DIM; k0 += BK) {
        __syncthreads();
        As[ak + 0][ar]      = a0.x; As[ak + 1][ar]      = a0.y;
        As[ak + 2][ar]      = a0.z; As[ak + 3][ar]      = a0.w;
        As[ak + 0][ar + 64] = a1.x; As[ak + 1][ar + 64] = a1.y;
        As[ak + 2][ar + 64] = a1.z; As[ak + 3][ar + 64] = a1.w;
        *reinterpret_cast<float4*>(&Bs[br][bc])     = b0;
        *reinterpret_cast<float4*>(&Bs[br + 8][bc]) = b1;
        __syncthreads();

        int kn = k0 + BK;
        if (kn < DIM) {  // prefetch next tile while computing
            a0 = z4; a1 = z4;
            if (r0 < M) a0 = *reinterpret_cast<const float4*>(A + (size_t)r0 * DIM + kn + ak);
            if (r1 < M) a1 = *reinterpret_cast<const float4*>(A + (size_t)r1 * DIM + kn + ak);
            b0 = *reinterpret_cast<const float4*>(W + (size_t)(kn + br) * DIM + bn + bc);
            b1 = *reinterpret_cast<const float4*>(W + (size_t)(kn + br + 8) * DIM + bn + bc);
        }

#pragma unroll
        for (int kk = 0; kk < BK; ++kk) {
            float4 x0 = *reinterpret_cast<const float4*>(&As[kk][ty * 8]);
            float4 x1 = *reinterpret_cast<const float4*>(&As[kk][ty * 8 + 4]);
            float4 y0 = *reinterpret_cast<const float4*>(&Bs[kk][tx * 8]);
            float4 y1 = *reinterpret_cast<const float4*>(&Bs[kk][tx * 8 + 4]);
            float ra[8] = {x0.x, x0.y, x0.z, x0.w, x1.x, x1.y, x1.z, x1.w};
            float rb[8] = {y0.x, y0.y, y0.z, y0.w, y1.x, y1.y, y1.z, y1.w};
#pragma unroll
            for (int i = 0; i < 8; i++)
#pragma unroll
                for (int j = 0; j < 8; j++)
                    acc[i][j] = fmaf(ra[i], rb[j], acc[i][j]);
        }
    }

    // epilogue: bias (+ relu), guarded rows; N=512 always exact in columns
#pragma unroll
    for (int i = 0; i < 8; i++) {
        int r = bm + ty * 8 + i;
        if (r >= M) continue;
        float* Crow = C + (size_t)r * DIM + bn + tx * 8;
        const float* bp = bias + bn + tx * 8;
        float4 v0, v1;
        v0.x = acc[i][0] + __ldg(bp + 0); v0.y = acc[i][1] + __ldg(bp + 1);
        v0.z = acc[i][2] + __ldg(bp + 2); v0.w = acc[i][3] + __ldg(bp + 3);
        v1.x = acc[i][4] + __ldg(bp + 4); v1.y = acc[i][5] + __ldg(bp + 5);
        v1.z = acc[i][6] + __ldg(bp + 6); v1.w = acc[i][7] + __ldg(bp + 7);
        if (relu) {
            v0.x = fmaxf(v0.x, 0.f); v0.y = fmaxf(v0.y, 0.f);
            v0.z = fmaxf(v0.z, 0.f); v0.w = fmaxf(v0.w, 0.f);
            v1.x = fmaxf(v1.x, 0.f); v1.y = fmaxf(v1.y, 0.f);
            v1.z = fmaxf(v1.z, 0.f); v1.w = fmaxf(v1.w, 0.f);
        }
        *reinterpret_cast<float4*>(Crow)     = v0;
        *reinterpret_cast<float4*>(Crow + 4) = v1;
    }
}

// ---------------------------------------------------------------------------
// Scatter-add:  acc[sidx[e]] += norm[e] * feat[gidx[e]]
// Vector reduction via inline PTX (red.global.add.v4.f32, PTX ISA 8.1+,
// sm_90+) — avoids dependence on the atomicAdd(float4*) header overload.
// shift flags subtract the dst-min (cidx shift in the reference)
// ---------------------------------------------------------------------------
__global__ __launch_bounds__(256) void k_scatter(
    const float* __restrict__ feat, float* __restrict__ acc,
    const int* __restrict__ gidx, const int* __restrict__ sidx,
    const float* __restrict__ norm, int gshift, int sshift)
{
    long long tid = (long long)blockIdx.x * blockDim.x + threadIdx.x;
    const long long total = (long long)NE * (DIM / 4);
    if (tid >= total) return;
    int e = (int)(tid >> 7);          // DIM/4 = 128 column-groups per edge
    int c = ((int)tid & 127) << 2;
    int mv = g_minv;
    int g = __ldg(gidx + e) - (gshift ? mv : 0);
    int s = __ldg(sidx + e) - (sshift ? mv : 0);
    float nv = __ldg(norm + e);
    float4 v = *reinterpret_cast<const float4*>(feat + (size_t)g * DIM + c);
    v.x *= nv; v.y *= nv; v.z *= nv; v.w *= nv;
    float* p = acc + (size_t)s * DIM + c;
    asm volatile("red.global.add.v4.f32 [%0], {%1, %2, %3, %4};"
                 :: "l"(p), "f"(v.x), "f"(v.y), "f"(v.z), "f"(v.w)
                 : "memory");
}

// ---------------------------------------------------------------------------
// Final heads epilogue: std = softplus(pre); final = noise*std + mean
// ---------------------------------------------------------------------------
__global__ void k_mix(const float* __restrict__ pre, const float* __restrict__ noise,
                      const float* __restrict__ mean, float* __restrict__ ostd,
                      float* __restrict__ ofin, size_t n)
{
    size_t i = (size_t)blockIdx.x * blockDim.x + threadIdx.x;
    size_t stride = (size_t)gridDim.x * blockDim.x;
    for (; i < n; i += stride) {
        float x = pre[i];
        float sp = fmaxf(x, 0.f) + log1pf(expf(-fabsf(x)));  // stable softplus
        ostd[i] = sp;
        ofin[i] = fmaf(noise[i], sp, mean[i]);
    }
}

// ---------------------------------------------------------------------------
// Host orchestration
// ---------------------------------------------------------------------------
static void run_gemm(const float* A, const float* W, const float* bias,
                     float* C, int M, bool relu) {
    dim3 grid(DIM / 128, (M + 127) / 128);
    k_gemm<<<grid, 256>>>(A, W, bias, C, M, relu ? 1 : 0);
}

static void run_ln(const float* in, float* out, const float* w, const float* b,
                   const float* cnt, int N) {
    k_ln<<<N, 128>>>(in, out, w, b, cnt, N);
}

struct MlpParams {
    const float *ln0w, *ln0b, *W1, *b1, *ln1w, *ln1b, *W2, *b2;
};

// AllSet MLP: LN -> Linear+ReLU -> LN -> Linear (+optional final ReLU)
// result lands in t2 (t1 is scratch; `in` may not alias t1/t2)
static void run_mlp(const float* in, float* t1, float* t2, const MlpParams& P,
                    int k, int N, bool relu_out, const float* cnt) {
    const size_t DD = (size_t)DIM * DIM;
    run_ln(in, t1, P.ln0w + (size_t)k * DIM, P.ln0b + (size_t)k * DIM, cnt, N);
    run_gemm(t1, P.W1 + (size_t)k * DD, P.b1 + (size_t)k * DIM, t2, N, true);
    run_ln(t2, t1, P.ln1w + (size_t)k * DIM, P.ln1b + (size_t)k * DIM, nullptr, N);
    run_gemm(t1, P.W2 + (size_t)k * DD, P.b2 + (size_t)k * DIM, t2, N, relu_out);
}

extern "C" void kernel_launch(void* const* d_in, const int* in_sizes, int n_in,
                              void* d_out, int out_size) {
    const float* x     = (const float*)d_in[0];
    const int*   eidx  = (const int*)  d_in[1];
    const float* norm  = (const float*)d_in[2];
    MlpParams P;
    P.ln0w = (const float*)d_in[3];
    P.ln0b = (const float*)d_in[4];
    P.W1   = (const float*)d_in[5];
    P.b1   = (const float*)d_in[6];
    P.ln1w = (const float*)d_in[7];
    P.ln1b = (const float*)d_in[8];
    P.W2   = (const float*)d_in[9];
    P.b2   = (const float*)d_in[10];
    const float* eW1    = (const float*)d_in[11];
    const float* eb1    = (const float*)d_in[12];
    const float* eW2    = (const float*)d_in[13];
    const float* eb2    = (const float*)d_in[14];
    const float* noiseN = (const float*)d_in[15];
    const float* noiseH = (const float*)d_in[16];
    float* out = (float*)d_out;

    const int* src = eidx;       // node index per incidence
    const int* dst = eidx + NE;  // hyperedge index per incidence

    float *n0, *n1, *n2, *h0, *h1, *h2, *cE, *cV;
    cudaGetSymbolAddress((void**)&n0, g_n0);
    cudaGetSymbolAddress((void**)&n1, g_n1);
    cudaGetSymbolAddress((void**)&n2, g_n2);
    cudaGetSymbolAddress((void**)&h0, g_h0);
    cudaGetSymbolAddress((void**)&h1, g_h1);
    cudaGetSymbolAddress((void**)&h2, g_h2);
    cudaGetSymbolAddress((void**)&cE, g_cntE);
    cudaGetSymbolAddress((void**)&cV, g_cntV);

    const size_t ND = (size_t)NN * DIM;
    const size_t HD = (size_t)NH * DIM;

    // --- graph preprocessing (recomputed every call; deterministic) ---
    k_init_min<<<1, 1>>>();
    k_min_reduce<<<256, 256>>>(dst, NE);
    k_zero4<<<64, 256>>>((float4*)cE, NH / 4);
    k_zero4<<<64, 256>>>((float4*)cV, NN / 4);
    k_hist<<<(NE + 255) / 256, 256>>>(dst, cE, NE, 1);
    k_hist<<<(NE + 255) / 256, 256>>>(src, cV, NE, 0);

    const int SC_BLOCKS = (int)(((long long)NE * (DIM / 4) + 255) / 256);

    // --- 2 layers of (V2E half-conv, E2V half-conv) ---
    for (int layer = 0; layer < 2; ++layer) {
        const float* inN = (layer == 0) ? x : n2;
        int m = 4 * layer;

        // V2E: enc-MLP on nodes -> scatter to hyperedges -> dec-MLP on HE
        run_mlp(inN, n0, n1, P, m + 0, NN, true, nullptr);            // enc in n1
        k_zero4<<<4096, 256>>>((float4*)h0, HD / 4);
        k_scatter<<<SC_BLOCKS, 256>>>(n1, h0, src, dst, norm, 0, 1);  // sum in h0
        run_mlp(h0, h1, h2, P, m + 1, NH, true, cE);                  // x_he in h2

        // E2V: enc-MLP on HE -> scatter to nodes -> dec-MLP on nodes
        run_mlp(h2, h0, h1, P, m + 2, NH, true, nullptr);             // enc in h1
        k_zero4<<<4096, 256>>>((float4*)n0, ND / 4);
        k_scatter<<<SC_BLOCKS, 256>>>(h1, n0, dst, src, norm, 1, 0);  // sum in n0
        run_mlp(n0, n1, n2, P, m + 3, NN, true, cV);                  // x_node in n2
    }

    // --- heads ---
    const size_t DD = (size_t)DIM * DIM;
    float* oFinN  = out;
    float* oMeanN = out + ND;
    float* oStdN  = out + 2 * ND;
    float* oFinH  = out + 3 * ND;
    float* oMeanH = out + 3 * ND + HD;
    float* oStdH  = out + 3 * ND + 2 * HD;

    // node mean (head 0)
    run_gemm(n2, eW1 + 0 * DD, eb1 + 0 * DIM, n0, NN, true);
    run_gemm(n0, eW2 + 0 * DD, eb2 + 0 * DIM, oMeanN, NN, false);
    // node std-pre (head 1)
    run_gemm(n2, eW1 + 1 * DD, eb1 + 1 * DIM, n0, NN, true);
    run_gemm(n0, eW2 + 1 * DD, eb2 + 1 * DIM, n1, NN, false);
    k_mix<<<8192, 256>>>(n1, noiseN, oMeanN, oStdN, oFinN, ND);

    // HE mean (head 2)
    run_gemm(h2, eW1 + 2 * DD, eb1 + 2 * DIM, h0, NH, true);
    run_gemm(h0, eW2 + 2 * DD, eb2 + 2 * DIM, oMeanH, NH, false);
    // HE std-pre (head 3)
    run_gemm(h2, eW1 + 3 * DD, eb1 + 3 * DIM, h0, NH, true);
    run_gemm(h0, eW2 + 3 * DD, eb2 + 3 * DIM, h1, NH, false);
    k_mix<<<4096, 256>>>(h1, noiseH, oMeanH, oStdH, oFinH, HD);

    (void)in_sizes; (void)n_in; (void)out_size;
}

// round 8
// speedup vs baseline: 1.7728x; 1.7728x over previous
#include <cuda_runtime.h>
#include <cuda_bf16.h>
#include <math.h>
#include <stdint.h>

// ---------------------------------------------------------------------------
// Problem constants (fixed by the dataset)
// ---------------------------------------------------------------------------
#define NN 50000      // nodes
#define NH 10000      // hyperedges
#define NE 250000     // incidences
#define DIM 512       // feature dim

// ---------------------------------------------------------------------------
// Scratch (static __device__ arrays; no allocation allowed)
// ---------------------------------------------------------------------------
__device__ float g_n0[(size_t)NN * DIM];
__device__ float g_n1[(size_t)NN * DIM];
__device__ float g_n2[(size_t)NN * DIM];
__device__ float g_h0[(size_t)NH * DIM];
__device__ float g_h1[(size_t)NH * DIM];
__device__ float g_h2[(size_t)NH * DIM];
__device__ float g_cntE[NH];
__device__ float g_cntV[NN];
__device__ int   g_minv;

// ---------------------------------------------------------------------------
// Small utility kernels
// ---------------------------------------------------------------------------
__global__ void k_init_min() { g_minv = 0x7fffffff; }

__global__ void k_min_reduce(const int* __restrict__ idx, int n) {
    int v = 0x7fffffff;
    for (int i = blockIdx.x * blockDim.x + threadIdx.x; i < n;
         i += gridDim.x * blockDim.x)
        v = min(v, __ldg(idx + i));
#pragma unroll
    for (int o = 16; o > 0; o >>= 1) v = min(v, __shfl_xor_sync(0xffffffffu, v, o));
    if ((threadIdx.x & 31) == 0) atomicMin(&g_minv, v);
}

__global__ void k_zero4(float4* __restrict__ p, size_t n4) {
    size_t i = (size_t)blockIdx.x * blockDim.x + threadIdx.x;
    size_t stride = (size_t)gridDim.x * blockDim.x;
    float4 z = make_float4(0.f, 0.f, 0.f, 0.f);
    for (; i < n4; i += stride) p[i] = z;
}

__global__ void k_hist(const int* __restrict__ idx, float* __restrict__ cnt,
                       int n, int shift) {
    int i = blockIdx.x * blockDim.x + threadIdx.x;
    if (i < n) {
        int s = __ldg(idx + i) - (shift ? g_minv : 0);
        atomicAdd(&cnt[s], 1.f);
    }
}

// ---------------------------------------------------------------------------
// LayerNorm over D=512, optional per-row prescale by 1/max(cnt,1)
// ---------------------------------------------------------------------------
__global__ __launch_bounds__(128) void k_ln(
    const float* __restrict__ in, float* __restrict__ out,
    const float* __restrict__ w, const float* __restrict__ b,
    const float* __restrict__ cnt, int N)
{
    int row = blockIdx.x;
    if (row >= N) return;
    int t = threadIdx.x;

    float scale = 1.f;
    if (cnt) scale = 1.f / fmaxf(__ldg(cnt + row), 1.f);

    float4 v = reinterpret_cast<const float4*>(in + (size_t)row * DIM)[t];
    v.x *= scale; v.y *= scale; v.z *= scale; v.w *= scale;

    float s  = v.x + v.y + v.z + v.w;
    float ss = v.x * v.x + v.y * v.y + v.z * v.z + v.w * v.w;
#pragma unroll
    for (int o = 16; o > 0; o >>= 1) {
        s  += __shfl_xor_sync(0xffffffffu, s, o);
        ss += __shfl_xor_sync(0xffffffffu, ss, o);
    }
    __shared__ float sh_s[4], sh_ss[4];
    int wid = t >> 5;
    if ((t & 31) == 0) { sh_s[wid] = s; sh_ss[wid] = ss; }
    __syncthreads();
    s  = sh_s[0] + sh_s[1] + sh_s[2] + sh_s[3];
    ss = sh_ss[0] + sh_ss[1] + sh_ss[2] + sh_ss[3];

    float mu   = s * (1.f / DIM);
    float var  = ss * (1.f / DIM) - mu * mu;
    float rstd = rsqrtf(var + 1e-5f);

    float4 wv = reinterpret_cast<const float4*>(w)[t];
    float4 bv = reinterpret_cast<const float4*>(b)[t];
    float4 o;
    o.x = (v.x - mu) * rstd * wv.x + bv.x;
    o.y = (v.y - mu) * rstd * wv.y + bv.y;
    o.z = (v.z - mu) * rstd * wv.z + bv.z;
    o.w = (v.w - mu) * rstd * wv.w + bv.w;
    reinterpret_cast<float4*>(out + (size_t)row * DIM)[t] = o;
}

// ---------------------------------------------------------------------------
// Split-bf16 tensor-core GEMM (fp32-class accuracy):
//   a = a_hi + a_lo (each bf16); C += ah*bh + ah*bl + al*bh  (fp32 accum)
// C[M,512] = A[M,512] @ W[512,512] + bias (+ReLU)
// 128x128x32 block tile, 8 warps (2x4), 64x32 warp tile, m16n8k16 bf16 mma.
// Packed .b32 = 2 consecutive-k bf16 -> fragment indexing identical to the
// tf32 m16n8k8 scheme. A smem [m][kpair] stride 36 (hi: cols 0-15, lo: 16-31);
// W smem [kpair][n] stride 136 (hi: rows 0-15, lo: rows 16-31). Conflict-free.
// ---------------------------------------------------------------------------
__device__ __forceinline__ void split_pack(float f0, float f1,
                                           uint32_t& hi, uint32_t& lo) {
    __nv_bfloat16 h0 = __float2bfloat16(f0);
    __nv_bfloat16 h1 = __float2bfloat16(f1);
    float r0 = f0 - __bfloat162float(h0);
    float r1 = f1 - __bfloat162float(h1);
    __nv_bfloat16 l0 = __float2bfloat16(r0);
    __nv_bfloat16 l1 = __float2bfloat16(r1);
    hi = (uint32_t)__bfloat16_as_ushort(h0) |
         ((uint32_t)__bfloat16_as_ushort(h1) << 16);
    lo = (uint32_t)__bfloat16_as_ushort(l0) |
         ((uint32_t)__bfloat16_as_ushort(l1) << 16);
}

__device__ __forceinline__ void mma_bf16(float* c, const uint32_t* a,
                                         const uint32_t* b) {
    asm volatile(
        "mma.sync.aligned.m16n8k16.row.col.f32.bf16.bf16.f32 "
        "{%0,%1,%2,%3}, {%4,%5,%6,%7}, {%8,%9}, {%0,%1,%2,%3};"
        : "+f"(c[0]), "+f"(c[1]), "+f"(c[2]), "+f"(c[3])
        : "r"(a[0]), "r"(a[1]), "r"(a[2]), "r"(a[3]), "r"(b[0]), "r"(b[1]));
}

__global__ __launch_bounds__(256) void k_gemm_tc(
    const float* __restrict__ A, const float* __restrict__ W,
    const float* __restrict__ bias, float* __restrict__ C,
    int M, int relu)
{
    constexpr int BM = 128, BN = 128;
    constexpr int ASTR = 36;    // packed words per A row (16 hi + 16 lo + pad)
    constexpr int BSTR = 136;   // words per B kpair-row (128 n + pad)
    __shared__ uint32_t As[BM * ASTR];
    __shared__ uint32_t Bs[32 * BSTR];   // kpair rows: 0-15 hi, 16-31 lo

    const int t    = threadIdx.x;
    const int bm   = blockIdx.y * BM;
    const int bn   = blockIdx.x * BN;
    const int w    = t >> 5;
    const int lane = t & 31;
    const int g    = lane >> 2;   // group id (0..7)
    const int tig  = lane & 3;    // thread in group (0..3)
    const int m0   = (w & 1) * 64;    // warp m-offset in block tile
    const int n0   = (w >> 1) * 32;   // warp n-offset in block tile

    // gmem->smem load mapping
    const int ar = t >> 3;          // 0..31, A row within group of 32
    const int ak = (t & 7) << 2;    // 0..28, A k-offset (float4)
    const int ap = (t & 7) << 1;    // packed-word offset = ak/2
    const int br = t >> 5;          // 0..7,  W kpair-row
    const int bc = (t & 31) << 2;   // 0..124, W n-offset (float4)

    float acc[4][4][4];
#pragma unroll
    for (int mf = 0; mf < 4; mf++)
#pragma unroll
        for (int nf = 0; nf < 4; nf++)
#pragma unroll
            for (int i = 0; i < 4; i++) acc[mf][nf][i] = 0.f;

    const float4 z4 = make_float4(0.f, 0.f, 0.f, 0.f);
    float4 pa[4];        // A: 4 row-quarters
    float4 pb[2][2];     // B: j in {0,1} (kpair=br+8j), two k-rows each

    // preload k0 = 0
#pragma unroll
    for (int j = 0; j < 4; j++) {
        int r = bm + ar + 32 * j;
        pa[j] = (r < M) ? *reinterpret_cast<const float4*>(A + (size_t)r * DIM + ak) : z4;
    }
#pragma unroll
    for (int j = 0; j < 2; j++) {
        int k2 = 2 * (br + 8 * j);
        pb[j][0] = *reinterpret_cast<const float4*>(W + (size_t)k2 * DIM + bn + bc);
        pb[j][1] = *reinterpret_cast<const float4*>(W + (size_t)(k2 + 1) * DIM + bn + bc);
    }

    for (int k0 = 0; k0 < DIM; k0 += 32) {
        __syncthreads();   // previous compute done before overwriting smem
#pragma unroll
        for (int j = 0; j < 4; j++) {
            uint32_t h0, l0, h1, l1;
            split_pack(pa[j].x, pa[j].y, h0, l0);
            split_pack(pa[j].z, pa[j].w, h1, l1);
            uint32_t* d = &As[(ar + 32 * j) * ASTR + ap];
            d[0] = h0; d[1] = h1; d[16] = l0; d[17] = l1;
        }
#pragma unroll
        for (int j = 0; j < 2; j++) {
            int kp = br + 8 * j;
            const float* w0 = &pb[j][0].x;
            const float* w1 = &pb[j][1].x;
            uint32_t* eh = &Bs[kp * BSTR + bc];
            uint32_t* el = &Bs[(kp + 16) * BSTR + bc];
#pragma unroll
            for (int i = 0; i < 4; i++) {
                uint32_t h, l;
                split_pack(w0[i], w1[i], h, l);  // low half = even k
                eh[i] = h; el[i] = l;
            }
        }
        __syncthreads();

        int kn = k0 + 32;
        if (kn < DIM) {  // prefetch next tile into registers over the MMAs
#pragma unroll
            for (int j = 0; j < 4; j++) {
                int r = bm + ar + 32 * j;
                pa[j] = (r < M) ? *reinterpret_cast<const float4*>(A + (size_t)r * DIM + kn + ak) : z4;
            }
#pragma unroll
            for (int j = 0; j < 2; j++) {
                int k2 = kn + 2 * (br + 8 * j);
                pb[j][0] = *reinterpret_cast<const float4*>(W + (size_t)k2 * DIM + bn + bc);
                pb[j][1] = *reinterpret_cast<const float4*>(W + (size_t)(k2 + 1) * DIM + bn + bc);
            }
        }

#pragma unroll
        for (int ks = 0; ks < 2; ks++) {
            const int kkp = ks * 8;   // packed-word k offset (= 16 floats)
            uint32_t bh[4][2], bl[4][2];
#pragma unroll
            for (int nf = 0; nf < 4; nf++) {
                int bi = (kkp + tig) * BSTR + n0 + nf * 8 + g;
                bh[nf][0] = Bs[bi];
                bh[nf][1] = Bs[bi + 4 * BSTR];
                bl[nf][0] = Bs[bi + 16 * BSTR];
                bl[nf][1] = Bs[bi + 20 * BSTR];
            }
#pragma unroll
            for (int mf = 0; mf < 4; mf++) {
                int am = (m0 + mf * 16 + g) * ASTR + kkp + tig;
                uint32_t ah[4], al[4];
                ah[0] = As[am];            ah[1] = As[am + 8 * ASTR];
                ah[2] = As[am + 4];        ah[3] = As[am + 8 * ASTR + 4];
                al[0] = As[am + 16];       al[1] = As[am + 8 * ASTR + 16];
                al[2] = As[am + 20];       al[3] = As[am + 8 * ASTR + 20];
#pragma unroll
                for (int nf = 0; nf < 4; nf++) {
                    mma_bf16(acc[mf][nf], ah, bh[nf]);
                    mma_bf16(acc[mf][nf], ah, bl[nf]);
                    mma_bf16(acc[mf][nf], al, bh[nf]);
                }
            }
        }
    }

    // epilogue: c0:(g, 2tig) c1:(g, 2tig+1) c2:(g+8, 2tig) c3:(g+8, 2tig+1)
#pragma unroll
    for (int mf = 0; mf < 4; mf++) {
        int row0 = bm + m0 + mf * 16 + g;
#pragma unroll
        for (int nf = 0; nf < 4; nf++) {
            int col = bn + n0 + nf * 8 + tig * 2;
            float bv0 = __ldg(bias + col), bv1 = __ldg(bias + col + 1);
            float v0 = acc[mf][nf][0] + bv0, v1 = acc[mf][nf][1] + bv1;
            float v2 = acc[mf][nf][2] + bv0, v3 = acc[mf][nf][3] + bv1;
            if (relu) {
                v0 = fmaxf(v0, 0.f); v1 = fmaxf(v1, 0.f);
                v2 = fmaxf(v2, 0.f); v3 = fmaxf(v3, 0.f);
            }
            if (row0 < M)
                *reinterpret_cast<float2*>(C + (size_t)row0 * DIM + col) = make_float2(v0, v1);
            if (row0 + 8 < M)
                *reinterpret_cast<float2*>(C + (size_t)(row0 + 8) * DIM + col) = make_float2(v2, v3);
        }
    }
}

// ---------------------------------------------------------------------------
// Scatter-add:  acc[sidx[e]] += norm[e] * feat[gidx[e]]  (red.global.v4.f32)
// ---------------------------------------------------------------------------
__global__ __launch_bounds__(256) void k_scatter(
    const float* __restrict__ feat, float* __restrict__ acc,
    const int* __restrict__ gidx, const int* __restrict__ sidx,
    const float* __restrict__ norm, int gshift, int sshift)
{
    long long tid = (long long)blockIdx.x * blockDim.x + threadIdx.x;
    const long long total = (long long)NE * (DIM / 4);
    if (tid >= total) return;
    int e = (int)(tid >> 7);          // DIM/4 = 128 column-groups per edge
    int c = ((int)tid & 127) << 2;
    int mv = g_minv;
    int g = __ldg(gidx + e) - (gshift ? mv : 0);
    int s = __ldg(sidx + e) - (sshift ? mv : 0);
    float nv = __ldg(norm + e);
    float4 v = *reinterpret_cast<const float4*>(feat + (size_t)g * DIM + c);
    v.x *= nv; v.y *= nv; v.z *= nv; v.w *= nv;
    float* p = acc + (size_t)s * DIM + c;
    asm volatile("red.global.add.v4.f32 [%0], {%1, %2, %3, %4};"
                 :: "l"(p), "f"(v.x), "f"(v.y), "f"(v.z), "f"(v.w)
                 : "memory");
}

// ---------------------------------------------------------------------------
// Final heads epilogue: std = softplus(pre); final = noise*std + mean
// ---------------------------------------------------------------------------
__global__ void k_mix(const float* __restrict__ pre, const float* __restrict__ noise,
                      const float* __restrict__ mean, float* __restrict__ ostd,
                      float* __restrict__ ofin, size_t n)
{
    size_t i = (size_t)blockIdx.x * blockDim.x + threadIdx.x;
    size_t stride = (size_t)gridDim.x * blockDim.x;
    for (; i < n; i += stride) {
        float x = pre[i];
        float sp = fmaxf(x, 0.f) + log1pf(expf(-fabsf(x)));  // stable softplus
        ostd[i] = sp;
        ofin[i] = fmaf(noise[i], sp, mean[i]);
    }
}

// ---------------------------------------------------------------------------
// Host orchestration
// ---------------------------------------------------------------------------
static void run_gemm(const float* A, const float* W, const float* bias,
                     float* C, int M, bool relu) {
    dim3 grid(DIM / 128, (M + 127) / 128);
    k_gemm_tc<<<grid, 256>>>(A, W, bias, C, M, relu ? 1 : 0);
}

static void run_ln(const float* in, float* out, const float* w, const float* b,
                   const float* cnt, int N) {
    k_ln<<<N, 128>>>(in, out, w, b, cnt, N);
}

struct MlpParams {
    const float *ln0w, *ln0b, *W1, *b1, *ln1w, *ln1b, *W2, *b2;
};

// AllSet MLP: LN -> Linear+ReLU -> LN -> Linear (+optional final ReLU)
static void run_mlp(const float* in, float* t1, float* t2, const MlpParams& P,
                    int k, int N, bool relu_out, const float* cnt) {
    const size_t DD = (size_t)DIM * DIM;
    run_ln(in, t1, P.ln0w + (size_t)k * DIM, P.ln0b + (size_t)k * DIM, cnt, N);
    run_gemm(t1, P.W1 + (size_t)k * DD, P.b1 + (size_t)k * DIM, t2, N, true);
    run_ln(t2, t1, P.ln1w + (size_t)k * DIM, P.ln1b + (size_t)k * DIM, nullptr, N);
    run_gemm(t1, P.W2 + (size_t)k * DD, P.b2 + (size_t)k * DIM, t2, N, relu_out);
}

extern "C" void kernel_launch(void* const* d_in, const int* in_sizes, int n_in,
                              void* d_out, int out_size) {
    const float* x     = (const float*)d_in[0];
    const int*   eidx  = (const int*)  d_in[1];
    const float* norm  = (const float*)d_in[2];
    MlpParams P;
    P.ln0w = (const float*)d_in[3];
    P.ln0b = (const float*)d_in[4];
    P.W1   = (const float*)d_in[5];
    P.b1   = (const float*)d_in[6];
    P.ln1w = (const float*)d_in[7];
    P.ln1b = (const float*)d_in[8];
    P.W2   = (const float*)d_in[9];
    P.b2   = (const float*)d_in[10];
    const float* eW1    = (const float*)d_in[11];
    const float* eb1    = (const float*)d_in[12];
    const float* eW2    = (const float*)d_in[13];
    const float* eb2    = (const float*)d_in[14];
    const float* noiseN = (const float*)d_in[15];
    const float* noiseH = (const float*)d_in[16];
    float* out = (float*)d_out;

    const int* src = eidx;       // node index per incidence
    const int* dst = eidx + NE;  // hyperedge index per incidence

    float *n0, *n1, *n2, *h0, *h1, *h2, *cE, *cV;
    cudaGetSymbolAddress((void**)&n0, g_n0);
    cudaGetSymbolAddress((void**)&n1, g_n1);
    cudaGetSymbolAddress((void**)&n2, g_n2);
    cudaGetSymbolAddress((void**)&h0, g_h0);
    cudaGetSymbolAddress((void**)&h1, g_h1);
    cudaGetSymbolAddress((void**)&h2, g_h2);
    cudaGetSymbolAddress((void**)&cE, g_cntE);
    cudaGetSymbolAddress((void**)&cV, g_cntV);

    const size_t ND = (size_t)NN * DIM;
    const size_t HD = (size_t)NH * DIM;

    // --- graph preprocessing (recomputed every call; deterministic) ---
    k_init_min<<<1, 1>>>();
    k_min_reduce<<<256, 256>>>(dst, NE);
    k_zero4<<<64, 256>>>((float4*)cE, NH / 4);
    k_zero4<<<64, 256>>>((float4*)cV, NN / 4);
    k_hist<<<(NE + 255) / 256, 256>>>(dst, cE, NE, 1);
    k_hist<<<(NE + 255) / 256, 256>>>(src, cV, NE, 0);

    const int SC_BLOCKS = (int)(((long long)NE * (DIM / 4) + 255) / 256);

    // --- 2 layers of (V2E half-conv, E2V half-conv) ---
    for (int layer = 0; layer < 2; ++layer) {
        const float* inN = (layer == 0) ? x : n2;
        int m = 4 * layer;

        // V2E: enc-MLP on nodes -> scatter to hyperedges -> dec-MLP on HE
        run_mlp(inN, n0, n1, P, m + 0, NN, true, nullptr);            // enc in n1
        k_zero4<<<4096, 256>>>((float4*)h0, HD / 4);
        k_scatter<<<SC_BLOCKS, 256>>>(n1, h0, src, dst, norm, 0, 1);  // sum in h0
        run_mlp(h0, h1, h2, P, m + 1, NH, true, cE);                  // x_he in h2

        // E2V: enc-MLP on HE -> scatter to nodes -> dec-MLP on nodes
        run_mlp(h2, h0, h1, P, m + 2, NH, true, nullptr);             // enc in h1
        k_zero4<<<4096, 256>>>((float4*)n0, ND / 4);
        k_scatter<<<SC_BLOCKS, 256>>>(h1, n0, dst, src, norm, 1, 0);  // sum in n0
        run_mlp(n0, n1, n2, P, m + 3, NN, true, cV);                  // x_node in n2
    }

    // --- heads ---
    const size_t DD = (size_t)DIM * DIM;
    float* oFinN  = out;
    float* oMeanN = out + ND;
    float* oStdN  = out + 2 * ND;
    float* oFinH  = out + 3 * ND;
    float* oMeanH = out + 3 * ND + HD;
    float* oStdH  = out + 3 * ND + 2 * HD;

    // node mean (head 0)
    run_gemm(n2, eW1 + 0 * DD, eb1 + 0 * DIM, n0, NN, true);
    run_gemm(n0, eW2 + 0 * DD, eb2 + 0 * DIM, oMeanN, NN, false);
    // node std-pre (head 1)
    run_gemm(n2, eW1 + 1 * DD, eb1 + 1 * DIM, n0, NN, true);
    run_gemm(n0, eW2 + 1 * DD, eb2 + 1 * DIM, n1, NN, false);
    k_mix<<<8192, 256>>>(n1, noiseN, oMeanN, oStdN, oFinN, ND);

    // HE mean (head 2)
    run_gemm(h2, eW1 + 2 * DD, eb1 + 2 * DIM, h0, NH, true);
    run_gemm(h0, eW2 + 2 * DD, eb2 + 2 * DIM, oMeanH, NH, false);
    // HE std-pre (head 3)
    run_gemm(h2, eW1 + 3 * DD, eb1 + 3 * DIM, h0, NH, true);
    run_gemm(h0, eW2 + 3 * DD, eb2 + 3 * DIM, h1, NH, false);
    k_mix<<<4096, 256>>>(h1, noiseH, oMeanH, oStdH, oFinH, HD);

    (void)in_sizes; (void)n_in; (void)out_size;
}

// round 9
// speedup vs baseline: 1.7740x; 1.0007x over previous
#include <cuda_runtime.h>
#include <cuda_bf16.h>
#include <math.h>
#include <stdint.h>

// ---------------------------------------------------------------------------
// Problem constants (fixed by the dataset)
// ---------------------------------------------------------------------------
#define NN 50000      // nodes
#define NH 10000      // hyperedges
#define NE 250000     // incidences
#define DIM 512       // feature dim

// ---------------------------------------------------------------------------
// Scratch (static __device__ arrays; no allocation allowed)
// ---------------------------------------------------------------------------
__device__ float g_n0[(size_t)NN * DIM];
__device__ float g_n1[(size_t)NN * DIM];
__device__ float g_n2[(size_t)NN * DIM];
__device__ float g_h0[(size_t)NH * DIM];
__device__ float g_h1[(size_t)NH * DIM];
__device__ float g_h2[(size_t)NH * DIM];
__device__ float g_cntE[NH];
__device__ float g_cntV[NN];
__device__ int   g_minv;

// ---------------------------------------------------------------------------
// Small utility kernels
// ---------------------------------------------------------------------------
__global__ void k_init_min() { g_minv = 0x7fffffff; }

__global__ void k_min_reduce(const int* __restrict__ idx, int n) {
    int v = 0x7fffffff;
    for (int i = blockIdx.x * blockDim.x + threadIdx.x; i < n;
         i += gridDim.x * blockDim.x)
        v = min(v, __ldg(idx + i));
#pragma unroll
    for (int o = 16; o > 0; o >>= 1) v = min(v, __shfl_xor_sync(0xffffffffu, v, o));
    if ((threadIdx.x & 31) == 0) atomicMin(&g_minv, v);
}

__global__ void k_zero4(float4* __restrict__ p, size_t n4) {
    size_t i = (size_t)blockIdx.x * blockDim.x + threadIdx.x;
    size_t stride = (size_t)gridDim.x * blockDim.x;
    float4 z = make_float4(0.f, 0.f, 0.f, 0.f);
    for (; i < n4; i += stride) p[i] = z;
}

__global__ void k_hist(const int* __restrict__ idx, float* __restrict__ cnt,
                       int n, int shift) {
    int i = blockIdx.x * blockDim.x + threadIdx.x;
    if (i < n) {
        int s = __ldg(idx + i) - (shift ? g_minv : 0);
        atomicAdd(&cnt[s], 1.f);
    }
}

// ---------------------------------------------------------------------------
// LayerNorm over D=512, optional per-row prescale by 1/max(cnt,1)
// ---------------------------------------------------------------------------
__global__ __launch_bounds__(128) void k_ln(
    const float* __restrict__ in, float* __restrict__ out,
    const float* __restrict__ w, const float* __restrict__ b,
    const float* __restrict__ cnt, int N)
{
    int row = blockIdx.x;
    if (row >= N) return;
    int t = threadIdx.x;

    float scale = 1.f;
    if (cnt) scale = 1.f / fmaxf(__ldg(cnt + row), 1.f);

    float4 v = reinterpret_cast<const float4*>(in + (size_t)row * DIM)[t];
    v.x *= scale; v.y *= scale; v.z *= scale; v.w *= scale;

    float s  = v.x + v.y + v.z + v.w;
    float ss = v.x * v.x + v.y * v.y + v.z * v.z + v.w * v.w;
#pragma unroll
    for (int o = 16; o > 0; o >>= 1) {
        s  += __shfl_xor_sync(0xffffffffu, s, o);
        ss += __shfl_xor_sync(0xffffffffu, ss, o);
    }
    __shared__ float sh_s[4], sh_ss[4];
    int wid = t >> 5;
    if ((t & 31) == 0) { sh_s[wid] = s; sh_ss[wid] = ss; }
    __syncthreads();
    s  = sh_s[0] + sh_s[1] + sh_s[2] + sh_s[3];
    ss = sh_ss[0] + sh_ss[1] + sh_ss[2] + sh_ss[3];

    float mu   = s * (1.f / DIM);
    float var  = ss * (1.f / DIM) - mu * mu;
    float rstd = rsqrtf(var + 1e-5f);

    float4 wv = reinterpret_cast<const float4*>(w)[t];
    float4 bv = reinterpret_cast<const float4*>(b)[t];
    float4 o;
    o.x = (v.x - mu) * rstd * wv.x + bv.x;
    o.y = (v.y - mu) * rstd * wv.y + bv.y;
    o.z = (v.z - mu) * rstd * wv.z + bv.z;
    o.w = (v.w - mu) * rstd * wv.w + bv.w;
    reinterpret_cast<float4*>(out + (size_t)row * DIM)[t] = o;
}

// ---------------------------------------------------------------------------
// Split-bf16 tensor-core GEMM (fp32-class accuracy):
//   a = a_hi + a_lo (each bf16); C += ah*bh + ah*bl + al*bh  (fp32 accum)
// C[M,512] = A[M,512] @ W[512,512] + bias (+ReLU)
// 128x128x32 block tile, 8 warps (2x4), 64x32 warp tile, m16n8k16 bf16 mma.
// Packed .b32 = 2 consecutive-k bf16 -> fragment indexing identical to the
// tf32 m16n8k8 scheme. A smem [m][kpair] stride 36 (hi: cols 0-15, lo: 16-31);
// W smem [kpair][n] stride 136 (hi: rows 0-15, lo: rows 16-31). Conflict-free.
// ---------------------------------------------------------------------------
__device__ __forceinline__ void split_pack(float f0, float f1,
                                           uint32_t& hi, uint32_t& lo) {
    __nv_bfloat16 h0 = __float2bfloat16(f0);
    __nv_bfloat16 h1 = __float2bfloat16(f1);
    float r0 = f0 - __bfloat162float(h0);
    float r1 = f1 - __bfloat162float(h1);
    __nv_bfloat16 l0 = __float2bfloat16(r0);
    __nv_bfloat16 l1 = __float2bfloat16(r1);
    hi = (uint32_t)__bfloat16_as_ushort(h0) |
         ((uint32_t)__bfloat16_as_ushort(h1) << 16);
    lo = (uint32_t)__bfloat16_as_ushort(l0) |
         ((uint32_t)__bfloat16_as_ushort(l1) << 16);
}

__device__ __forceinline__ void mma_bf16(float* c, const uint32_t* a,
                                         const uint32_t* b) {
    asm volatile(
        "mma.sync.aligned.m16n8k16.row.col.f32.bf16.bf16.f32 "
        "{%0,%1,%2,%3}, {%4,%5,%6,%7}, {%8,%9}, {%0,%1,%2,%3};"
        : "+f"(c[0]), "+f"(c[1]), "+f"(c[2]), "+f"(c[3])
        : "r"(a[0]), "r"(a[1]), "r"(a[2]), "r"(a[3]), "r"(b[0]), "r"(b[1]));
}

__global__ __launch_bounds__(256) void k_gemm_tc(
    const float* __restrict__ A, const float* __restrict__ W,
    const float* __restrict__ bias, float* __restrict__ C,
    int M, int relu)
{
    constexpr int BM = 128, BN = 128;
    constexpr int ASTR = 36;    // packed words per A row (16 hi + 16 lo + pad)
    constexpr int BSTR = 136;   // words per B kpair-row (128 n + pad)
    __shared__ uint32_t As[BM * ASTR];
    __shared__ uint32_t Bs[32 * BSTR];   // kpair rows: 0-15 hi, 16-31 lo

    const int t    = threadIdx.x;
    const int bm   = blockIdx.y * BM;
    const int bn   = blockIdx.x * BN;
    const int w    = t >> 5;
    const int lane = t & 31;
    const int g    = lane >> 2;   // group id (0..7)
    const int tig  = lane & 3;    // thread in group (0..3)
    const int m0   = (w & 1) * 64;    // warp m-offset in block tile
    const int n0   = (w >> 1) * 32;   // warp n-offset in block tile

    // gmem->smem load mapping
    const int ar = t >> 3;          // 0..31, A row within group of 32
    const int ak = (t & 7) << 2;    // 0..28, A k-offset (float4)
    const int ap = (t & 7) << 1;    // packed-word offset = ak/2
    const int br = t >> 5;          // 0..7,  W kpair-row
    const int bc = (t & 31) << 2;   // 0..124, W n-offset (float4)

    float acc[4][4][4];
#pragma unroll
    for (int mf = 0; mf < 4; mf++)
#pragma unroll
        for (int nf = 0; nf < 4; nf++)
#pragma unroll
            for (int i = 0; i < 4; i++) acc[mf][nf][i] = 0.f;

    const float4 z4 = make_float4(0.f, 0.f, 0.f, 0.f);
    float4 pa[4];        // A: 4 row-quarters
    float4 pb[2][2];     // B: j in {0,1} (kpair=br+8j), two k-rows each

    // preload k0 = 0
#pragma unroll
    for (int j = 0; j < 4; j++) {
        int r = bm + ar + 32 * j;
        pa[j] = (r < M) ? *reinterpret_cast<const float4*>(A + (size_t)r * DIM + ak) : z4;
    }
#pragma unroll
    for (int j = 0; j < 2; j++) {
        int k2 = 2 * (br + 8 * j);
        pb[j][0] = *reinterpret_cast<const float4*>(W + (size_t)k2 * DIM + bn + bc);
        pb[j][1] = *reinterpret_cast<const float4*>(W + (size_t)(k2 + 1) * DIM + bn + bc);
    }

    for (int k0 = 0; k0 < DIM; k0 += 32) {
        __syncthreads();   // previous compute done before overwriting smem
#pragma unroll
        for (int j = 0; j < 4; j++) {
            uint32_t h0, l0, h1, l1;
            split_pack(pa[j].x, pa[j].y, h0, l0);
            split_pack(pa[j].z, pa[j].w, h1, l1);
            uint32_t* d = &As[(ar + 32 * j) * ASTR + ap];
            d[0] = h0; d[1] = h1; d[16] = l0; d[17] = l1;
        }
#pragma unroll
        for (int j = 0; j < 2; j++) {
            int kp = br + 8 * j;
            const float* w0 = &pb[j][0].x;
            const float* w1 = &pb[j][1].x;
            uint32_t* eh = &Bs[kp * BSTR + bc];
            uint32_t* el = &Bs[(kp + 16) * BSTR + bc];
#pragma unroll
            for (int i = 0; i < 4; i++) {
                uint32_t h, l;
                split_pack(w0[i], w1[i], h, l);  // low half = even k
                eh[i] = h; el[i] = l;
            }
        }
        __syncthreads();

        int kn = k0 + 32;
        if (kn < DIM) {  // prefetch next tile into registers over the MMAs
#pragma unroll
            for (int j = 0; j < 4; j++) {
                int r = bm + ar + 32 * j;
                pa[j] = (r < M) ? *reinterpret_cast<const float4*>(A + (size_t)r * DIM + kn + ak) : z4;
            }
#pragma unroll
            for (int j = 0; j < 2; j++) {
                int k2 = kn + 2 * (br + 8 * j);
                pb[j][0] = *reinterpret_cast<const float4*>(W + (size_t)k2 * DIM + bn + bc);
                pb[j][1] = *reinterpret_cast<const float4*>(W + (size_t)(k2 + 1) * DIM + bn + bc);
            }
        }

#pragma unroll
        for (int ks = 0; ks < 2; ks++) {
            const int kkp = ks * 8;   // packed-word k offset (= 16 floats)
            uint32_t bh[4][2], bl[4][2];
#pragma unroll
            for (int nf = 0; nf < 4; nf++) {
                int bi = (kkp + tig) * BSTR + n0 + nf * 8 + g;
                bh[nf][0] = Bs[bi];
                bh[nf][1] = Bs[bi + 4 * BSTR];
                bl[nf][0] = Bs[bi + 16 * BSTR];
                bl[nf][1] = Bs[bi + 20 * BSTR];
            }
#pragma unroll
            for (int mf = 0; mf < 4; mf++) {
                int am = (m0 + mf * 16 + g) * ASTR + kkp + tig;
                uint32_t ah[4], al[4];
                ah[0] = As[am];            ah[1] = As[am + 8 * ASTR];
                ah[2] = As[am + 4];        ah[3] = As[am + 8 * ASTR + 4];
                al[0] = As[am + 16];       al[1] = As[am + 8 * ASTR + 16];
                al[2] = As[am + 20];       al[3] = As[am + 8 * ASTR + 20];
#pragma unroll
                for (int nf = 0; nf < 4; nf++) {
                    mma_bf16(acc[mf][nf], ah, bh[nf]);
                    mma_bf16(acc[mf][nf], ah, bl[nf]);
                    mma_bf16(acc[mf][nf], al, bh[nf]);
                }
            }
        }
    }

    // epilogue: c0:(g, 2tig) c1:(g, 2tig+1) c2:(g+8, 2tig) c3:(g+8, 2tig+1)
#pragma unroll
    for (int mf = 0; mf < 4; mf++) {
        int row0 = bm + m0 + mf * 16 + g;
#pragma unroll
        for (int nf = 0; nf < 4; nf++) {
            int col = bn + n0 + nf * 8 + tig * 2;
            float bv0 = __ldg(bias + col), bv1 = __ldg(bias + col + 1);
            float v0 = acc[mf][nf][0] + bv0, v1 = acc[mf][nf][1] + bv1;
            float v2 = acc[mf][nf][2] + bv0, v3 = acc[mf][nf][3] + bv1;
            if (relu) {
                v0 = fmaxf(v0, 0.f); v1 = fmaxf(v1, 0.f);
                v2 = fmaxf(v2, 0.f); v3 = fmaxf(v3, 0.f);
            }
            if (row0 < M)
                *reinterpret_cast<float2*>(C + (size_t)row0 * DIM + col) = make_float2(v0, v1);
            if (row0 + 8 < M)
                *reinterpret_cast<float2*>(C + (size_t)(row0 + 8) * DIM + col) = make_float2(v2, v3);
        }
    }
}

// ---------------------------------------------------------------------------
// Scatter-add:  acc[sidx[e]] += norm[e] * feat[gidx[e]]  (red.global.v4.f32)
// ---------------------------------------------------------------------------
__global__ __launch_bounds__(256) void k_scatter(
    const float* __restrict__ feat, float* __restrict__ acc,
    const int* __restrict__ gidx, const int* __restrict__ sidx,
    const float* __restrict__ norm, int gshift, int sshift)
{
    long long tid = (long long)blockIdx.x * blockDim.x + threadIdx.x;
    const long long total = (long long)NE * (DIM / 4);
    if (tid >= total) return;
    int e = (int)(tid >> 7);          // DIM/4 = 128 column-groups per edge
    int c = ((int)tid & 127) << 2;
    int mv = g_minv;
    int g = __ldg(gidx + e) - (gshift ? mv : 0);
    int s = __ldg(sidx + e) - (sshift ? mv : 0);
    float nv = __ldg(norm + e);
    float4 v = *reinterpret_cast<const float4*>(feat + (size_t)g * DIM + c);
    v.x *= nv; v.y *= nv; v.z *= nv; v.w *= nv;
    float* p = acc + (size_t)s * DIM + c;
    asm volatile("red.global.add.v4.f32 [%0], {%1, %2, %3, %4};"
                 :: "l"(p), "f"(v.x), "f"(v.y), "f"(v.z), "f"(v.w)
                 : "memory");
}

// ---------------------------------------------------------------------------
// Final heads epilogue: std = softplus(pre); final = noise*std + mean
// ---------------------------------------------------------------------------
__global__ void k_mix(const float* __restrict__ pre, const float* __restrict__ noise,
                      const float* __restrict__ mean, float* __restrict__ ostd,
                      float* __restrict__ ofin, size_t n)
{
    size_t i = (size_t)blockIdx.x * blockDim.x + threadIdx.x;
    size_t stride = (size_t)gridDim.x * blockDim.x;
    for (; i < n; i += stride) {
        float x = pre[i];
        float sp = fmaxf(x, 0.f) + log1pf(expf(-fabsf(x)));  // stable softplus
        ostd[i] = sp;
        ofin[i] = fmaf(noise[i], sp, mean[i]);
    }
}

// ---------------------------------------------------------------------------
// Host orchestration
// ---------------------------------------------------------------------------
static void run_gemm(const float* A, const float* W, const float* bias,
                     float* C, int M, bool relu) {
    dim3 grid(DIM / 128, (M + 127) / 128);
    k_gemm_tc<<<grid, 256>>>(A, W, bias, C, M, relu ? 1 : 0);
}

static void run_ln(const float* in, float* out, const float* w, const float* b,
                   const float* cnt, int N) {
    k_ln<<<N, 128>>>(in, out, w, b, cnt, N);
}

struct MlpParams {
    const float *ln0w, *ln0b, *W1, *b1, *ln1w, *ln1b, *W2, *b2;
};

// AllSet MLP: LN -> Linear+ReLU -> LN -> Linear (+optional final ReLU)
static void run_mlp(const float* in, float* t1, float* t2, const MlpParams& P,
                    int k, int N, bool relu_out, const float* cnt) {
    const size_t DD = (size_t)DIM * DIM;
    run_ln(in, t1, P.ln0w + (size_t)k * DIM, P.ln0b + (size_t)k * DIM, cnt, N);
    run_gemm(t1, P.W1 + (size_t)k * DD, P.b1 + (size_t)k * DIM, t2, N, true);
    run_ln(t2, t1, P.ln1w + (size_t)k * DIM, P.ln1b + (size_t)k * DIM, nullptr, N);
    run_gemm(t1, P.W2 + (size_t)k * DD, P.b2 + (size_t)k * DIM, t2, N, relu_out);
}

extern "C" void kernel_launch(void* const* d_in, const int* in_sizes, int n_in,
                              void* d_out, int out_size) {
    const float* x     = (const float*)d_in[0];
    const int*   eidx  = (const int*)  d_in[1];
    const float* norm  = (const float*)d_in[2];
    MlpParams P;
    P.ln0w = (const float*)d_in[3];
    P.ln0b = (const float*)d_in[4];
    P.W1   = (const float*)d_in[5];
    P.b1   = (const float*)d_in[6];
    P.ln1w = (const float*)d_in[7];
    P.ln1b = (const float*)d_in[8];
    P.W2   = (const float*)d_in[9];
    P.b2   = (const float*)d_in[10];
    const float* eW1    = (const float*)d_in[11];
    const float* eb1    = (const float*)d_in[12];
    const float* eW2    = (const float*)d_in[13];
    const float* eb2    = (const float*)d_in[14];
    const float* noiseN = (const float*)d_in[15];
    const float* noiseH = (const float*)d_in[16];
    float* out = (float*)d_out;

    const int* src = eidx;       // node index per incidence
    const int* dst = eidx + NE;  // hyperedge index per incidence

    float *n0, *n1, *n2, *h0, *h1, *h2, *cE, *cV;
    cudaGetSymbolAddress((void**)&n0, g_n0);
    cudaGetSymbolAddress((void**)&n1, g_n1);
    cudaGetSymbolAddress((void**)&n2, g_n2);
    cudaGetSymbolAddress((void**)&h0, g_h0);
    cudaGetSymbolAddress((void**)&h1, g_h1);
    cudaGetSymbolAddress((void**)&h2, g_h2);
    cudaGetSymbolAddress((void**)&cE, g_cntE);
    cudaGetSymbolAddress((void**)&cV, g_cntV);

    const size_t ND = (size_t)NN * DIM;
    const size_t HD = (size_t)NH * DIM;

    // --- graph preprocessing (recomputed every call; deterministic) ---
    k_init_min<<<1, 1>>>();
    k_min_reduce<<<256, 256>>>(dst, NE);
    k_zero4<<<64, 256>>>((float4*)cE, NH / 4);
    k_zero4<<<64, 256>>>((float4*)cV, NN / 4);
    k_hist<<<(NE + 255) / 256, 256>>>(dst, cE, NE, 1);
    k_hist<<<(NE + 255) / 256, 256>>>(src, cV, NE, 0);

    const int SC_BLOCKS = (int)(((long long)NE * (DIM / 4) + 255) / 256);

    // --- 2 layers of (V2E half-conv, E2V half-conv) ---
    for (int layer = 0; layer < 2; ++layer) {
        const float* inN = (layer == 0) ? x : n2;
        int m = 4 * layer;

        // V2E: enc-MLP on nodes -> scatter to hyperedges -> dec-MLP on HE
        run_mlp(inN, n0, n1, P, m + 0, NN, true, nullptr);            // enc in n1
        k_zero4<<<4096, 256>>>((float4*)h0, HD / 4);
        k_scatter<<<SC_BLOCKS, 256>>>(n1, h0, src, dst, norm, 0, 1);  // sum in h0
        run_mlp(h0, h1, h2, P, m + 1, NH, true, cE);                  // x_he in h2

        // E2V: enc-MLP on HE -> scatter to nodes -> dec-MLP on nodes
        run_mlp(h2, h0, h1, P, m + 2, NH, true, nullptr);             // enc in h1
        k_zero4<<<4096, 256>>>((float4*)n0, ND / 4);
        k_scatter<<<SC_BLOCKS, 256>>>(h1, n0, dst, src, norm, 1, 0);  // sum in n0
        run_mlp(n0, n1, n2, P, m + 3, NN, true, cV);                  // x_node in n2
    }

    // --- heads ---
    const size_t DD = (size_t)DIM * DIM;
    float* oFinN  = out;
    float* oMeanN = out + ND;
    float* oStdN  = out + 2 * ND;
    float* oFinH  = out + 3 * ND;
    float* oMeanH = out + 3 * ND + HD;
    float* oStdH  = out + 3 * ND + 2 * HD;

    // node mean (head 0)
    run_gemm(n2, eW1 + 0 * DD, eb1 + 0 * DIM, n0, NN, true);
    run_gemm(n0, eW2 + 0 * DD, eb2 + 0 * DIM, oMeanN, NN, false);
    // node std-pre (head 1)
    run_gemm(n2, eW1 + 1 * DD, eb1 + 1 * DIM, n0, NN, true);
    run_gemm(n0, eW2 + 1 * DD, eb2 + 1 * DIM, n1, NN, false);
    k_mix<<<8192, 256>>>(n1, noiseN, oMeanN, oStdN, oFinN, ND);

    // HE mean (head 2)
    run_gemm(h2, eW1 + 2 * DD, eb1 + 2 * DIM, h0, NH, true);
    run_gemm(h0, eW2 + 2 * DD, eb2 + 2 * DIM, oMeanH, NH, false);
    // HE std-pre (head 3)
    run_gemm(h2, eW1 + 3 * DD, eb1 + 3 * DIM, h0, NH, true);
    run_gemm(h0, eW2 + 3 * DD, eb2 + 3 * DIM, h1, NH, false);
    k_mix<<<4096, 256>>>(h1, noiseH, oMeanH, oStdH, oFinH, HD);

    (void)in_sizes; (void)n_in; (void)out_size;
}

// round 11
// speedup vs baseline: 1.8748x; 1.0568x over previous
#include <cuda_runtime.h>
#include <cuda_bf16.h>
#include <math.h>
#include <stdint.h>

#define NN 50000
#define NH 10000
#define NE 250000
#define DIM 512

// ---------------------------------------------------------------------------
// Static scratch (no allocation allowed)
// ---------------------------------------------------------------------------
__device__ float g_n0[(size_t)NN * DIM];
__device__ float g_n1[(size_t)NN * DIM];
__device__ float g_n2[(size_t)NN * DIM];
__device__ float g_h0[(size_t)NH * DIM];
__device__ float g_h1[(size_t)NH * DIM];
__device__ float g_h2[(size_t)NH * DIM];
__device__ int   g_minv;
// CSR structures (rebuilt every call)
__device__ int g_cntE[NH], g_cntV[NN];
__device__ int g_curE[NH], g_curV[NN];
__device__ int g_rpE[NH + 1], g_rpV[NN + 1];
__device__ int g_colE[NE], g_colV[NE];

// ---------------------------------------------------------------------------
// Graph preprocessing
// ---------------------------------------------------------------------------
__global__ void k_init_min() { g_minv = 0x7fffffff; }

__global__ void k_min_reduce(const int* __restrict__ idx, int n) {
    int v = 0x7fffffff;
    for (int i = blockIdx.x * blockDim.x + threadIdx.x; i < n;
         i += gridDim.x * blockDim.x)
        v = min(v, __ldg(idx + i));
#pragma unroll
    for (int o = 16; o > 0; o >>= 1) v = min(v, __shfl_xor_sync(0xffffffffu, v, o));
    if ((threadIdx.x & 31) == 0) atomicMin(&g_minv, v);
}

__global__ void k_zero4(float4* __restrict__ p, size_t n4) {
    size_t i = (size_t)blockIdx.x * blockDim.x + threadIdx.x;
    size_t stride = (size_t)gridDim.x * blockDim.x;
    float4 z = make_float4(0.f, 0.f, 0.f, 0.f);
    for (; i < n4; i += stride) p[i] = z;
}

__global__ void k_cnt(const int* __restrict__ idx, int* __restrict__ cnt,
                      int n, int shift) {
    int i = blockIdx.x * blockDim.x + threadIdx.x;
    if (i < n) atomicAdd(&cnt[__ldg(idx + i) - (shift ? g_minv : 0)], 1);
}

// single-block exclusive scan of cnt[0..n) into rp[0..n], rp[n] = total
__global__ __launch_bounds__(1024) void k_scan(const int* __restrict__ cnt,
                                               int* __restrict__ rp, int n) {
    __shared__ int part[1024];
    int t = threadIdx.x;
    int C = (n + 1023) >> 10;
    int base = t * C;
    int sum = 0;
    for (int i = 0; i < C; i++)
        if (base + i < n) sum += cnt[base + i];
    part[t] = sum;
    __syncthreads();
    for (int o = 1; o < 1024; o <<= 1) {
        int v = (t >= o) ? part[t - o] : 0;
        __syncthreads();
        part[t] += v;
        __syncthreads();
    }
    int excl = (t == 0) ? 0 : part[t - 1];
    for (int i = 0; i < C; i++)
        if (base + i < n) { rp[base + i] = excl; excl += cnt[base + i]; }
    if (t == 1023) rp[n] = part[1023];
}

__global__ void k_fill(const int* __restrict__ idx, const int* __restrict__ rp,
                       int* __restrict__ cur, int* __restrict__ col,
                       int n, int shift) {
    int i = blockIdx.x * blockDim.x + threadIdx.x;
    if (i < n) {
        int s = __ldg(idx + i) - (shift ? g_minv : 0);
        int p = atomicAdd(&cur[s], 1);
        col[rp[s] + p] = i;
    }
}

// ---------------------------------------------------------------------------
// CSR segment-mean gather:  out[seg] = (1/max(len,1)) * sum_e norm[e]*feat[gidx[e]]
// one block (128 threads) per segment; thread owns 4 columns
// ---------------------------------------------------------------------------
__global__ __launch_bounds__(128) void k_gather(
    const float* __restrict__ feat, float* __restrict__ out,
    const int* __restrict__ rp, const int* __restrict__ col,
    const int* __restrict__ gidx, const float* __restrict__ norm, int gshift)
{
    int seg = blockIdx.x;
    int beg = rp[seg], end = rp[seg + 1];
    int t = threadIdx.x;
    int mv = g_minv;
    __shared__ int   se[128];
    __shared__ float sn[128];
    float4 acc = make_float4(0.f, 0.f, 0.f, 0.f);
    for (int base = beg; base < end; base += 128) {
        int nb = min(128, end - base);
        if (t < nb) {
            int e = __ldg(col + base + t);
            se[t] = __ldg(gidx + e) - (gshift ? mv : 0);
            sn[t] = __ldg(norm + e);
        }
        __syncthreads();
        for (int j = 0; j < nb; j++) {
            float4 v = *reinterpret_cast<const float4*>(
                feat + (size_t)se[j] * DIM + t * 4);
            float nv = sn[j];
            acc.x = fmaf(nv, v.x, acc.x);
            acc.y = fmaf(nv, v.y, acc.y);
            acc.z = fmaf(nv, v.z, acc.z);
            acc.w = fmaf(nv, v.w, acc.w);
        }
        __syncthreads();
    }
    float inv = 1.f / fmaxf((float)(end - beg), 1.f);
    acc.x *= inv; acc.y *= inv; acc.z *= inv; acc.w *= inv;
    *reinterpret_cast<float4*>(out + (size_t)seg * DIM + t * 4) = acc;
}

// ---------------------------------------------------------------------------
// Warp-per-row LayerNorm over D=512 (8 rows per 256-thread block)
// ---------------------------------------------------------------------------
__global__ __launch_bounds__(256) void k_ln(
    const float* __restrict__ in, float* __restrict__ out,
    const float* __restrict__ w, const float* __restrict__ b, int N)
{
    int warp = threadIdx.x >> 5, lane = threadIdx.x & 31;
    int row = blockIdx.x * 8 + warp;
    if (row >= N) return;
    const float4* ip = reinterpret_cast<const float4*>(in + (size_t)row * DIM);
    float4 v[4];
    float s = 0.f, ss = 0.f;
#pragma unroll
    for (int j = 0; j < 4; j++) {
        v[j] = ip[lane + 32 * j];
        s  += v[j].x + v[j].y + v[j].z + v[j].w;
        ss += v[j].x * v[j].x + v[j].y * v[j].y +
              v[j].z * v[j].z + v[j].w * v[j].w;
    }
#pragma unroll
    for (int o = 16; o > 0; o >>= 1) {
        s  += __shfl_xor_sync(0xffffffffu, s, o);
        ss += __shfl_xor_sync(0xffffffffu, ss, o);
    }
    float mu   = s * (1.f / DIM);
    float rstd = rsqrtf(ss * (1.f / DIM) - mu * mu + 1e-5f);
    float4* op = reinterpret_cast<float4*>(out + (size_t)row * DIM);
    const float4* wp = reinterpret_cast<const float4*>(w);
    const float4* bp = reinterpret_cast<const float4*>(b);
#pragma unroll
    for (int j = 0; j < 4; j++) {
        float4 wv = __ldg(wp + lane + 32 * j);
        float4 bv = __ldg(bp + lane + 32 * j);
        float4 o;
        o.x = (v[j].x - mu) * rstd * wv.x + bv.x;
        o.y = (v[j].y - mu) * rstd * wv.y + bv.y;
        o.z = (v[j].z - mu) * rstd * wv.z + bv.z;
        o.w = (v[j].w - mu) * rstd * wv.w + bv.w;
        op[lane + 32 * j] = o;
    }
}

// ---------------------------------------------------------------------------
// Split-bf16 tensor-core GEMM (UNCHANGED from the passing round-8 kernel)
// ---------------------------------------------------------------------------
__device__ __forceinline__ void split_pack(float f0, float f1,
                                           uint32_t& hi, uint32_t& lo) {
    __nv_bfloat16 h0 = __float2bfloat16(f0);
    __nv_bfloat16 h1 = __float2bfloat16(f1);
    float r0 = f0 - __bfloat162float(h0);
    float r1 = f1 - __bfloat162float(h1);
    __nv_bfloat16 l0 = __float2bfloat16(r0);
    __nv_bfloat16 l1 = __float2bfloat16(r1);
    hi = (uint32_t)__bfloat16_as_ushort(h0) |
         ((uint32_t)__bfloat16_as_ushort(h1) << 16);
    lo = (uint32_t)__bfloat16_as_ushort(l0) |
         ((uint32_t)__bfloat16_as_ushort(l1) << 16);
}

__device__ __forceinline__ void mma_bf16(float* c, const uint32_t* a,
                                         const uint32_t* b) {
    asm volatile(
        "mma.sync.aligned.m16n8k16.row.col.f32.bf16.bf16.f32 "
        "{%0,%1,%2,%3}, {%4,%5,%6,%7}, {%8,%9}, {%0,%1,%2,%3};"
        : "+f"(c[0]), "+f"(c[1]), "+f"(c[2]), "+f"(c[3])
        : "r"(a[0]), "r"(a[1]), "r"(a[2]), "r"(a[3]), "r"(b[0]), "r"(b[1]));
}

__global__ __launch_bounds__(256) void k_gemm_tc(
    const float* __restrict__ A, const float* __restrict__ W,
    const float* __restrict__ bias, float* __restrict__ C,
    int M, int relu)
{
    constexpr int BM = 128, BN = 128;
    constexpr int ASTR = 36;
    constexpr int BSTR = 136;
    __shared__ uint32_t As[BM * ASTR];
    __shared__ uint32_t Bs[32 * BSTR];

    const int t    = threadIdx.x;
    const int bm   = blockIdx.y * BM;
    const int bn   = blockIdx.x * BN;
    const int w    = t >> 5;
    const int lane = t & 31;
    const int g    = lane >> 2;
    const int tig  = lane & 3;
    const int m0   = (w & 1) * 64;
    const int n0   = (w >> 1) * 32;

    const int ar = t >> 3;
    const int ak = (t & 7) << 2;
    const int ap = (t & 7) << 1;
    const int br = t >> 5;
    const int bc = (t & 31) << 2;

    float acc[4][4][4];
#pragma unroll
    for (int mf = 0; mf < 4; mf++)
#pragma unroll
        for (int nf = 0; nf < 4; nf++)
#pragma unroll
            for (int i = 0; i < 4; i++) acc[mf][nf][i] = 0.f;

    const float4 z4 = make_float4(0.f, 0.f, 0.f, 0.f);
    float4 pa[4];
    float4 pb[2][2];

#pragma unroll
    for (int j = 0; j < 4; j++) {
        int r = bm + ar + 32 * j;
        pa[j] = (r < M) ? *reinterpret_cast<const float4*>(A + (size_t)r * DIM + ak) : z4;
    }
#pragma unroll
    for (int j = 0; j < 2; j++) {
        int k2 = 2 * (br + 8 * j);
        pb[j][0] = *reinterpret_cast<const float4*>(W + (size_t)k2 * DIM + bn + bc);
        pb[j][1] = *reinterpret_cast<const float4*>(W + (size_t)(k2 + 1) * DIM + bn + bc);
    }

    for (int k0 = 0; k0 < DIM; k0 += 32) {
        __syncthreads();
#pragma unroll
        for (int j = 0; j < 4; j++) {
            uint32_t h0, l0, h1, l1;
            split_pack(pa[j].x, pa[j].y, h0, l0);
            split_pack(pa[j].z, pa[j].w, h1, l1);
            uint32_t* d = &As[(ar + 32 * j) * ASTR + ap];
            d[0] = h0; d[1] = h1; d[16] = l0; d[17] = l1;
        }
#pragma unroll
        for (int j = 0; j < 2; j++) {
            int kp = br + 8 * j;
            const float* w0 = &pb[j][0].x;
            const float* w1 = &pb[j][1].x;
            uint32_t* eh = &Bs[kp * BSTR + bc];
            uint32_t* el = &Bs[(kp + 16) * BSTR + bc];
#pragma unroll
            for (int i = 0; i < 4; i++) {
                uint32_t h, l;
                split_pack(w0[i], w1[i], h, l);
                eh[i] = h; el[i] = l;
            }
        }
        __syncthreads();

        int kn = k0 + 32;
        if (kn < DIM) {
#pragma unroll
            for (int j = 0; j < 4; j++) {
                int r = bm + ar + 32 * j;
                pa[j] = (r < M) ? *reinterpret_cast<const float4*>(A + (size_t)r * DIM + kn + ak) : z4;
            }
#pragma unroll
            for (int j = 0; j < 2; j++) {
                int k2 = kn + 2 * (br + 8 * j);
                pb[j][0] = *reinterpret_cast<const float4*>(W + (size_t)k2 * DIM + bn + bc);
                pb[j][1] = *reinterpret_cast<const float4*>(W + (size_t)(k2 + 1) * DIM + bn + bc);
            }
        }

#pragma unroll
        for (int ks = 0; ks < 2; ks++) {
            const int kkp = ks * 8;
            uint32_t bh[4][2], bl[4][2];
#pragma unroll
            for (int nf = 0; nf < 4; nf++) {
                int bi = (kkp + tig) * BSTR + n0 + nf * 8 + g;
                bh[nf][0] = Bs[bi];
                bh[nf][1] = Bs[bi + 4 * BSTR];
                bl[nf][0] = Bs[bi + 16 * BSTR];
                bl[nf][1] = Bs[bi + 20 * BSTR];
            }
#pragma unroll
            for (int mf = 0; mf < 4; mf++) {
                int am = (m0 + mf * 16 + g) * ASTR + kkp + tig;
                uint32_t ah[4], al[4];
                ah[0] = As[am];            ah[1] = As[am + 8 * ASTR];
                ah[2] = As[am + 4];        ah[3] = As[am + 8 * ASTR + 4];
                al[0] = As[am + 16];       al[1] = As[am + 8 * ASTR + 16];
                al[2] = As[am + 20];       al[3] = As[am + 8 * ASTR + 20];
#pragma unroll
                for (int nf = 0; nf < 4; nf++) {
                    mma_bf16(acc[mf][nf], ah, bh[nf]);
                    mma_bf16(acc[mf][nf], ah, bl[nf]);
                    mma_bf16(acc[mf][nf], al, bh[nf]);
                }
            }
        }
    }

#pragma unroll
    for (int mf = 0; mf < 4; mf++) {
        int row0 = bm + m0 + mf * 16 + g;
#pragma unroll
        for (int nf = 0; nf < 4; nf++) {
            int col = bn + n0 + nf * 8 + tig * 2;
            float bv0 = __ldg(bias + col), bv1 = __ldg(bias + col + 1);
            float v0 = acc[mf][nf][0] + bv0, v1 = acc[mf][nf][1] + bv1;
            float v2 = acc[mf][nf][2] + bv0, v3 = acc[mf][nf][3] + bv1;
            if (relu) {
                v0 = fmaxf(v0, 0.f); v1 = fmaxf(v1, 0.f);
                v2 = fmaxf(v2, 0.f); v3 = fmaxf(v3, 0.f);
            }
            if (row0 < M)
                *reinterpret_cast<float2*>(C + (size_t)row0 * DIM + col) = make_float2(v0, v1);
            if (row0 + 8 < M)
                *reinterpret_cast<float2*>(C + (size_t)(row0 + 8) * DIM + col) = make_float2(v2, v3);
        }
    }
}

// ---------------------------------------------------------------------------
// Final heads epilogue
// ---------------------------------------------------------------------------
__global__ void k_mix(const float* __restrict__ pre, const float* __restrict__ noise,
                      const float* __restrict__ mean, float* __restrict__ ostd,
                      float* __restrict__ ofin, size_t n)
{
    size_t i = (size_t)blockIdx.x * blockDim.x + threadIdx.x;
    size_t stride = (size_t)gridDim.x * blockDim.x;
    for (; i < n; i += stride) {
        float x = pre[i];
        float sp = fmaxf(x, 0.f) + log1pf(expf(-fabsf(x)));
        ostd[i] = sp;
        ofin[i] = fmaf(noise[i], sp, mean[i]);
    }
}

// ---------------------------------------------------------------------------
// Host orchestration
// ---------------------------------------------------------------------------
static void run_gemm(const float* A, const float* W, const float* bias,
                     float* C, int M, bool relu) {
    dim3 grid(DIM / 128, (M + 127) / 128);
    k_gemm_tc<<<grid, 256>>>(A, W, bias, C, M, relu ? 1 : 0);
}

static void run_ln(const float* in, float* out, const float* w, const float* b,
                   int N) {
    k_ln<<<(N + 7) / 8, 256>>>(in, out, w, b, N);
}

struct MlpParams {
    const float *ln0w, *ln0b, *W1, *b1, *ln1w, *ln1b, *W2, *b2;
};

static void run_mlp(const float* in, float* t1, float* t2, const MlpParams& P,
                    int k, int N, bool relu_out) {
    const size_t DD = (size_t)DIM * DIM;
    run_ln(in, t1, P.ln0w + (size_t)k * DIM, P.ln0b + (size_t)k * DIM, N);
    run_gemm(t1, P.W1 + (size_t)k * DD, P.b1 + (size_t)k * DIM, t2, N, true);
    run_ln(t2, t1, P.ln1w + (size_t)k * DIM, P.ln1b + (size_t)k * DIM, N);
    run_gemm(t1, P.W2 + (size_t)k * DD, P.b2 + (size_t)k * DIM, t2, N, relu_out);
}

extern "C" void kernel_launch(void* const* d_in, const int* in_sizes, int n_in,
                              void* d_out, int out_size) {
    const float* x    = (const float*)d_in[0];
    const int*   eidx = (const int*)  d_in[1];
    const float* norm = (const float*)d_in[2];
    MlpParams P;
    P.ln0w = (const float*)d_in[3];
    P.ln0b = (const float*)d_in[4];
    P.W1   = (const float*)d_in[5];
    P.b1   = (const float*)d_in[6];
    P.ln1w = (const float*)d_in[7];
    P.ln1b = (const float*)d_in[8];
    P.W2   = (const float*)d_in[9];
    P.b2   = (const float*)d_in[10];
    const float* eW1    = (const float*)d_in[11];
    const float* eb1    = (const float*)d_in[12];
    const float* eW2    = (const float*)d_in[13];
    const float* eb2    = (const float*)d_in[14];
    const float* noiseN = (const float*)d_in[15];
    const float* noiseH = (const float*)d_in[16];
    float* out = (float*)d_out;

    const int* src = eidx;
    const int* dst = eidx + NE;

    float *n0, *n1, *n2, *h0, *h1, *h2;
    int *cntE, *cntV, *curE, *curV, *rpE, *rpV, *colE, *colV;
    cudaGetSymbolAddress((void**)&n0, g_n0);
    cudaGetSymbolAddress((void**)&n1, g_n1);
    cudaGetSymbolAddress((void**)&n2, g_n2);
    cudaGetSymbolAddress((void**)&h0, g_h0);
    cudaGetSymbolAddress((void**)&h1, g_h1);
    cudaGetSymbolAddress((void**)&h2, g_h2);
    cudaGetSymbolAddress((void**)&cntE, g_cntE);
    cudaGetSymbolAddress((void**)&cntV, g_cntV);
    cudaGetSymbolAddress((void**)&curE, g_curE);
    cudaGetSymbolAddress((void**)&curV, g_curV);
    cudaGetSymbolAddress((void**)&rpE, g_rpE);
    cudaGetSymbolAddress((void**)&rpV, g_rpV);
    cudaGetSymbolAddress((void**)&colE, g_colE);
    cudaGetSymbolAddress((void**)&colV, g_colV);

    const size_t ND = (size_t)NN * DIM;
    const size_t HD = (size_t)NH * DIM;

    // --- CSR build (both directions; once per call) ---
    k_init_min<<<1, 1>>>();
    k_min_reduce<<<256, 256>>>(dst, NE);
    k_zero4<<<32, 256>>>((float4*)cntE, NH / 4);
    k_zero4<<<64, 256>>>((float4*)cntV, NN / 4);
    k_zero4<<<32, 256>>>((float4*)curE, NH / 4);
    k_zero4<<<64, 256>>>((float4*)curV, NN / 4);
    k_cnt<<<(NE + 255) / 256, 256>>>(dst, cntE, NE, 1);
    k_cnt<<<(NE + 255) / 256, 256>>>(src, cntV, NE, 0);
    k_scan<<<1, 1024>>>(cntE, rpE, NH);
    k_scan<<<1, 1024>>>(cntV, rpV, NN);
    k_fill<<<(NE + 255) / 256, 256>>>(dst, rpE, curE, colE, NE, 1);
    k_fill<<<(NE + 255) / 256, 256>>>(src, rpV, curV, colV, NE, 0);

    // --- 2 layers of (V2E half-conv, E2V half-conv) ---
    for (int layer = 0; layer < 2; ++layer) {
        const float* inN = (layer == 0) ? x : n2;
        int m = 4 * layer;

        run_mlp(inN, n0, n1, P, m + 0, NN, true);                    // enc in n1
        k_gather<<<NH, 128>>>(n1, h0, rpE, colE, src, norm, 0);      // mean in h0
        run_mlp(h0, h1, h2, P, m + 1, NH, true);                     // x_he in h2

        run_mlp(h2, h0, h1, P, m + 2, NH, true);                     // enc in h1
        k_gather<<<NN, 128>>>(h1, n0, rpV, colV, dst, norm, 1);      // mean in n0
        run_mlp(n0, n1, n2, P, m + 3, NN, true);                     // x_node in n2
    }

    // --- heads ---
    const size_t DD = (size_t)DIM * DIM;
    float* oFinN  = out;
    float* oMeanN = out + ND;
    float* oStdN  = out + 2 * ND;
    float* oFinH  = out + 3 * ND;
    float* oMeanH = out + 3 * ND + HD;
    float* oStdH  = out + 3 * ND + 2 * HD;

    run_gemm(n2, eW1 + 0 * DD, eb1 + 0 * DIM, n0, NN, true);
    run_gemm(n0, eW2 + 0 * DD, eb2 + 0 * DIM, oMeanN, NN, false);
    run_gemm(n2, eW1 + 1 * DD, eb1 + 1 * DIM, n0, NN, true);
    run_gemm(n0, eW2 + 1 * DD, eb2 + 1 * DIM, n1, NN, false);
    k_mix<<<8192, 256>>>(n1, noiseN, oMeanN, oStdN, oFinN, ND);

    run_gemm(h2, eW1 + 2 * DD, eb1 + 2 * DIM, h0, NH, true);
    run_gemm(h0, eW2 + 2 * DD, eb2 + 2 * DIM, oMeanH, NH, false);
    run_gemm(h2, eW1 + 3 * DD, eb1 + 3 * DIM, h0, NH, true);
    run_gemm(h0, eW2 + 3 * DD, eb2 + 3 * DIM, h1, NH, false);
    k_mix<<<4096, 256>>>(h1, noiseH, oMeanH, oStdH, oFinH, HD);

    (void)in_sizes; (void)n_in; (void)out_size;
}

// round 12
// speedup vs baseline: 2.2055x; 1.1764x over previous
#include <cuda_runtime.h>
#include <cuda_bf16.h>
#include <math.h>
#include <stdint.h>

#define NN 50000
#define NH 10000
#define NE 250000
#define DIM 512

// ---------------------------------------------------------------------------
// Static scratch (no allocation allowed)
// ---------------------------------------------------------------------------
__device__ float g_n0[(size_t)NN * DIM];
__device__ float g_n1[(size_t)NN * DIM];
__device__ float g_n2[(size_t)NN * DIM];
__device__ float g_h0[(size_t)NH * DIM];
__device__ float g_h1[(size_t)NH * DIM];
__device__ float g_h2[(size_t)NH * DIM];
__device__ int   g_minv;
// CSR structures (rebuilt every call)
__device__ int g_cntE[NH], g_cntV[NN];
__device__ int g_curE[NH], g_curV[NN];
__device__ int g_rpE[NH + 1], g_rpV[NN + 1];
__device__ int g_colE[NE], g_colV[NE];

// ---------------------------------------------------------------------------
// Graph preprocessing
// ---------------------------------------------------------------------------
__global__ void k_init_min() { g_minv = 0x7fffffff; }

__global__ void k_min_reduce(const int* __restrict__ idx, int n) {
    int v = 0x7fffffff;
    for (int i = blockIdx.x * blockDim.x + threadIdx.x; i < n;
         i += gridDim.x * blockDim.x)
        v = min(v, __ldg(idx + i));
#pragma unroll
    for (int o = 16; o > 0; o >>= 1) v = min(v, __shfl_xor_sync(0xffffffffu, v, o));
    if ((threadIdx.x & 31) == 0) atomicMin(&g_minv, v);
}

__global__ void k_zero4(float4* __restrict__ p, size_t n4) {
    size_t i = (size_t)blockIdx.x * blockDim.x + threadIdx.x;
    size_t stride = (size_t)gridDim.x * blockDim.x;
    float4 z = make_float4(0.f, 0.f, 0.f, 0.f);
    for (; i < n4; i += stride) p[i] = z;
}

__global__ void k_cnt(const int* __restrict__ idx, int* __restrict__ cnt,
                      int n, int shift) {
    int i = blockIdx.x * blockDim.x + threadIdx.x;
    if (i < n) atomicAdd(&cnt[__ldg(idx + i) - (shift ? g_minv : 0)], 1);
}

// single-block exclusive scan of cnt[0..n) into rp[0..n], rp[n] = total
__global__ __launch_bounds__(1024) void k_scan(const int* __restrict__ cnt,
                                               int* __restrict__ rp, int n) {
    __shared__ int part[1024];
    int t = threadIdx.x;
    int C = (n + 1023) >> 10;
    int base = t * C;
    int sum = 0;
    for (int i = 0; i < C; i++)
        if (base + i < n) sum += cnt[base + i];
    part[t] = sum;
    __syncthreads();
    for (int o = 1; o < 1024; o <<= 1) {
        int v = (t >= o) ? part[t - o] : 0;
        __syncthreads();
        part[t] += v;
        __syncthreads();
    }
    int excl = (t == 0) ? 0 : part[t - 1];
    for (int i = 0; i < C; i++)
        if (base + i < n) { rp[base + i] = excl; excl += cnt[base + i]; }
    if (t == 1023) rp[n] = part[1023];
}

__global__ void k_fill(const int* __restrict__ idx, const int* __restrict__ rp,
                       int* __restrict__ cur, int* __restrict__ col,
                       int n, int shift) {
    int i = blockIdx.x * blockDim.x + threadIdx.x;
    if (i < n) {
        int s = __ldg(idx + i) - (shift ? g_minv : 0);
        int p = atomicAdd(&cur[s], 1);
        col[rp[s] + p] = i;
    }
}

// ---------------------------------------------------------------------------
// CSR segment-mean gather
// ---------------------------------------------------------------------------
__global__ __launch_bounds__(128) void k_gather(
    const float* __restrict__ feat, float* __restrict__ out,
    const int* __restrict__ rp, const int* __restrict__ col,
    const int* __restrict__ gidx, const float* __restrict__ norm, int gshift)
{
    int seg = blockIdx.x;
    int beg = rp[seg], end = rp[seg + 1];
    int t = threadIdx.x;
    int mv = g_minv;
    __shared__ int   se[128];
    __shared__ float sn[128];
    float4 acc = make_float4(0.f, 0.f, 0.f, 0.f);
    for (int base = beg; base < end; base += 128) {
        int nb = min(128, end - base);
        if (t < nb) {
            int e = __ldg(col + base + t);
            se[t] = __ldg(gidx + e) - (gshift ? mv : 0);
            sn[t] = __ldg(norm + e);
        }
        __syncthreads();
        for (int j = 0; j < nb; j++) {
            float4 v = *reinterpret_cast<const float4*>(
                feat + (size_t)se[j] * DIM + t * 4);
            float nv = sn[j];
            acc.x = fmaf(nv, v.x, acc.x);
            acc.y = fmaf(nv, v.y, acc.y);
            acc.z = fmaf(nv, v.z, acc.z);
            acc.w = fmaf(nv, v.w, acc.w);
        }
        __syncthreads();
    }
    float inv = 1.f / fmaxf((float)(end - beg), 1.f);
    acc.x *= inv; acc.y *= inv; acc.z *= inv; acc.w *= inv;
    *reinterpret_cast<float4*>(out + (size_t)seg * DIM + t * 4) = acc;
}

// ---------------------------------------------------------------------------
// Warp-per-row LayerNorm over D=512 (8 rows per 256-thread block)
// ---------------------------------------------------------------------------
__global__ __launch_bounds__(256) void k_ln(
    const float* __restrict__ in, float* __restrict__ out,
    const float* __restrict__ w, const float* __restrict__ b, int N)
{
    int warp = threadIdx.x >> 5, lane = threadIdx.x & 31;
    int row = blockIdx.x * 8 + warp;
    if (row >= N) return;
    const float4* ip = reinterpret_cast<const float4*>(in + (size_t)row * DIM);
    float4 v[4];
    float s = 0.f, ss = 0.f;
#pragma unroll
    for (int j = 0; j < 4; j++) {
        v[j] = ip[lane + 32 * j];
        s  += v[j].x + v[j].y + v[j].z + v[j].w;
        ss += v[j].x * v[j].x + v[j].y * v[j].y +
              v[j].z * v[j].z + v[j].w * v[j].w;
    }
#pragma unroll
    for (int o = 16; o > 0; o >>= 1) {
        s  += __shfl_xor_sync(0xffffffffu, s, o);
        ss += __shfl_xor_sync(0xffffffffu, ss, o);
    }
    float mu   = s * (1.f / DIM);
    float rstd = rsqrtf(ss * (1.f / DIM) - mu * mu + 1e-5f);
    float4* op = reinterpret_cast<float4*>(out + (size_t)row * DIM);
    const float4* wp = reinterpret_cast<const float4*>(w);
    const float4* bp = reinterpret_cast<const float4*>(b);
#pragma unroll
    for (int j = 0; j < 4; j++) {
        float4 wv = __ldg(wp + lane + 32 * j);
        float4 bv = __ldg(bp + lane + 32 * j);
        float4 o;
        o.x = (v[j].x - mu) * rstd * wv.x + bv.x;
        o.y = (v[j].y - mu) * rstd * wv.y + bv.y;
        o.z = (v[j].z - mu) * rstd * wv.z + bv.z;
        o.w = (v[j].w - mu) * rstd * wv.w + bv.w;
        op[lane + 32 * j] = o;
    }
}

// ---------------------------------------------------------------------------
// Split-bf16 tensor-core GEMM — DOUBLE-BUFFERED smem (one sync per K-iter)
// ---------------------------------------------------------------------------
#define ASTR 36
#define BSTR 136
#define A_WORDS (128 * ASTR)                 // 4608 words
#define SSTR (A_WORDS + 32 * BSTR)           // 8960 words per stage
#define GEMM_SMEM (2 * SSTR * 4)             // 71680 bytes

__device__ __forceinline__ void split_pack(float f0, float f1,
                                           uint32_t& hi, uint32_t& lo) {
    __nv_bfloat16 h0 = __float2bfloat16(f0);
    __nv_bfloat16 h1 = __float2bfloat16(f1);
    float r0 = f0 - __bfloat162float(h0);
    float r1 = f1 - __bfloat162float(h1);
    __nv_bfloat16 l0 = __float2bfloat16(r0);
    __nv_bfloat16 l1 = __float2bfloat16(r1);
    hi = (uint32_t)__bfloat16_as_ushort(h0) |
         ((uint32_t)__bfloat16_as_ushort(h1) << 16);
    lo = (uint32_t)__bfloat16_as_ushort(l0) |
         ((uint32_t)__bfloat16_as_ushort(l1) << 16);
}

__device__ __forceinline__ void mma_bf16(float* c, const uint32_t* a,
                                         const uint32_t* b) {
    asm volatile(
        "mma.sync.aligned.m16n8k16.row.col.f32.bf16.bf16.f32 "
        "{%0,%1,%2,%3}, {%4,%5,%6,%7}, {%8,%9}, {%0,%1,%2,%3};"
        : "+f"(c[0]), "+f"(c[1]), "+f"(c[2]), "+f"(c[3])
        : "r"(a[0]), "r"(a[1]), "r"(a[2]), "r"(a[3]), "r"(b[0]), "r"(b[1]));
}

__global__ __launch_bounds__(256, 2) void k_gemm_tc(
    const float* __restrict__ A, const float* __restrict__ W,
    const float* __restrict__ bias, float* __restrict__ C,
    int M, int relu)
{
    extern __shared__ uint32_t sm[];

    const int t    = threadIdx.x;
    const int bm   = blockIdx.y * 128;
    const int bn   = blockIdx.x * 128;
    const int w    = t >> 5;
    const int lane = t & 31;
    const int g    = lane >> 2;
    const int tig  = lane & 3;
    const int m0   = (w & 1) * 64;
    const int n0   = (w >> 1) * 32;

    const int ar = t >> 3;
    const int ak = (t & 7) << 2;
    const int ap = (t & 7) << 1;
    const int br = t >> 5;
    const int bc = (t & 31) << 2;

    float acc[4][4][4];
#pragma unroll
    for (int mf = 0; mf < 4; mf++)
#pragma unroll
        for (int nf = 0; nf < 4; nf++)
#pragma unroll
            for (int i = 0; i < 4; i++) acc[mf][nf][i] = 0.f;

    const float4 z4 = make_float4(0.f, 0.f, 0.f, 0.f);
    float4 pa[4];
    float4 pb[2][2];

    auto loadRegs = [&](int i) {
        int kk = i * 32;
#pragma unroll
        for (int j = 0; j < 4; j++) {
            int r = bm + ar + 32 * j;
            pa[j] = (r < M) ? *reinterpret_cast<const float4*>(
                                  A + (size_t)r * DIM + kk + ak)
                            : z4;
        }
#pragma unroll
        for (int j = 0; j < 2; j++) {
            int k2 = kk + 2 * (br + 8 * j);
            pb[j][0] = *reinterpret_cast<const float4*>(W + (size_t)k2 * DIM + bn + bc);
            pb[j][1] = *reinterpret_cast<const float4*>(W + (size_t)(k2 + 1) * DIM + bn + bc);
        }
    };
    auto storeStage = [&](int s) {
        uint32_t* S = sm + s * SSTR;
#pragma unroll
        for (int j = 0; j < 4; j++) {
            uint32_t h0, l0, h1, l1;
            split_pack(pa[j].x, pa[j].y, h0, l0);
            split_pack(pa[j].z, pa[j].w, h1, l1);
            uint32_t* d = S + (ar + 32 * j) * ASTR + ap;
            d[0] = h0; d[1] = h1; d[16] = l0; d[17] = l1;
        }
#pragma unroll
        for (int j = 0; j < 2; j++) {
            int kp = br + 8 * j;
            const float* w0 = &pb[j][0].x;
            const float* w1 = &pb[j][1].x;
            uint32_t* eh = S + A_WORDS + kp * BSTR + bc;
            uint32_t* el = eh + 16 * BSTR;
#pragma unroll
            for (int q = 0; q < 4; q++) {
                uint32_t h, l;
                split_pack(w0[q], w1[q], h, l);
                eh[q] = h; el[q] = l;
            }
        }
    };

    loadRegs(0);
    storeStage(0);
    __syncthreads();
    loadRegs(1);

    for (int i = 0; i < 16; i++) {
        const int cur = i & 1;
        if (i < 15) storeStage(cur ^ 1);   // regs hold tile i+1
        if (i < 14) loadRegs(i + 2);       // issue gmem loads; land during MMAs

        const uint32_t* SA = sm + cur * SSTR;
        const uint32_t* SB = SA + A_WORDS;
#pragma unroll
        for (int ks = 0; ks < 2; ks++) {
            const int kkp = ks * 8;
            uint32_t bh[4][2], bl[4][2];
#pragma unroll
            for (int nf = 0; nf < 4; nf++) {
                int bi = (kkp + tig) * BSTR + n0 + nf * 8 + g;
                bh[nf][0] = SB[bi];
                bh[nf][1] = SB[bi + 4 * BSTR];
                bl[nf][0] = SB[bi + 16 * BSTR];
                bl[nf][1] = SB[bi + 20 * BSTR];
            }
#pragma unroll
            for (int mf = 0; mf < 4; mf++) {
                int am = (m0 + mf * 16 + g) * ASTR + kkp + tig;
                uint32_t ah[4], al[4];
                ah[0] = SA[am];            ah[1] = SA[am + 8 * ASTR];
                ah[2] = SA[am + 4];        ah[3] = SA[am + 8 * ASTR + 4];
                al[0] = SA[am + 16];       al[1] = SA[am + 8 * ASTR + 16];
                al[2] = SA[am + 20];       al[3] = SA[am + 8 * ASTR + 20];
#pragma unroll
                for (int nf = 0; nf < 4; nf++) {
                    mma_bf16(acc[mf][nf], ah, bh[nf]);
                    mma_bf16(acc[mf][nf], ah, bl[nf]);
                    mma_bf16(acc[mf][nf], al, bh[nf]);
                }
            }
        }
        __syncthreads();
    }

#pragma unroll
    for (int mf = 0; mf < 4; mf++) {
        int row0 = bm + m0 + mf * 16 + g;
#pragma unroll
        for (int nf = 0; nf < 4; nf++) {
            int col = bn + n0 + nf * 8 + tig * 2;
            float bv0 = __ldg(bias + col), bv1 = __ldg(bias + col + 1);
            float v0 = acc[mf][nf][0] + bv0, v1 = acc[mf][nf][1] + bv1;
            float v2 = acc[mf][nf][2] + bv0, v3 = acc[mf][nf][3] + bv1;
            if (relu) {
                v0 = fmaxf(v0, 0.f); v1 = fmaxf(v1, 0.f);
                v2 = fmaxf(v2, 0.f); v3 = fmaxf(v3, 0.f);
            }
            if (row0 < M)
                *reinterpret_cast<float2*>(C + (size_t)row0 * DIM + col) = make_float2(v0, v1);
            if (row0 + 8 < M)
                *reinterpret_cast<float2*>(C + (size_t)(row0 + 8) * DIM + col) = make_float2(v2, v3);
        }
    }
}

// ---------------------------------------------------------------------------
// Final heads epilogue
// ---------------------------------------------------------------------------
__global__ void k_mix(const float* __restrict__ pre, const float* __restrict__ noise,
                      const float* __restrict__ mean, float* __restrict__ ostd,
                      float* __restrict__ ofin, size_t n)
{
    size_t i = (size_t)blockIdx.x * blockDim.x + threadIdx.x;
    size_t stride = (size_t)gridDim.x * blockDim.x;
    for (; i < n; i += stride) {
        float x = pre[i];
        float sp = fmaxf(x, 0.f) + log1pf(expf(-fabsf(x)));
        ostd[i] = sp;
        ofin[i] = fmaf(noise[i], sp, mean[i]);
    }
}

// ---------------------------------------------------------------------------
// Host orchestration
// ---------------------------------------------------------------------------
static void run_gemm(const float* A, const float* W, const float* bias,
                     float* C, int M, bool relu) {
    dim3 grid(DIM / 128, (M + 127) / 128);
    k_gemm_tc<<<grid, 256, GEMM_SMEM>>>(A, W, bias, C, M, relu ? 1 : 0);
}

static void run_ln(const float* in, float* out, const float* w, const float* b,
                   int N) {
    k_ln<<<(N + 7) / 8, 256>>>(in, out, w, b, N);
}

struct MlpParams {
    const float *ln0w, *ln0b, *W1, *b1, *ln1w, *ln1b, *W2, *b2;
};

static void run_mlp(const float* in, float* t1, float* t2, const MlpParams& P,
                    int k, int N, bool relu_out) {
    const size_t DD = (size_t)DIM * DIM;
    run_ln(in, t1, P.ln0w + (size_t)k * DIM, P.ln0b + (size_t)k * DIM, N);
    run_gemm(t1, P.W1 + (size_t)k * DD, P.b1 + (size_t)k * DIM, t2, N, true);
    run_ln(t2, t1, P.ln1w + (size_t)k * DIM, P.ln1b + (size_t)k * DIM, N);
    run_gemm(t1, P.W2 + (size_t)k * DD, P.b2 + (size_t)k * DIM, t2, N, relu_out);
}

extern "C" void kernel_launch(void* const* d_in, const int* in_sizes, int n_in,
                              void* d_out, int out_size) {
    const float* x    = (const float*)d_in[0];
    const int*   eidx = (const int*)  d_in[1];
    const float* norm = (const float*)d_in[2];
    MlpParams P;
    P.ln0w = (const float*)d_in[3];
    P.ln0b = (const float*)d_in[4];
    P.W1   = (const float*)d_in[5];
    P.b1   = (const float*)d_in[6];
    P.ln1w = (const float*)d_in[7];
    P.ln1b = (const float*)d_in[8];
    P.W2   = (const float*)d_in[9];
    P.b2   = (const float*)d_in[10];
    const float* eW1    = (const float*)d_in[11];
    const float* eb1    = (const float*)d_in[12];
    const float* eW2    = (const float*)d_in[13];
    const float* eb2    = (const float*)d_in[14];
    const float* noiseN = (const float*)d_in[15];
    const float* noiseH = (const float*)d_in[16];
    float* out = (float*)d_out;

    const int* src = eidx;
    const int* dst = eidx + NE;

    float *n0, *n1, *n2, *h0, *h1, *h2;
    int *cntE, *cntV, *curE, *curV, *rpE, *rpV, *colE, *colV;
    cudaGetSymbolAddress((void**)&n0, g_n0);
    cudaGetSymbolAddress((void**)&n1, g_n1);
    cudaGetSymbolAddress((void**)&n2, g_n2);
    cudaGetSymbolAddress((void**)&h0, g_h0);
    cudaGetSymbolAddress((void**)&h1, g_h1);
    cudaGetSymbolAddress((void**)&h2, g_h2);
    cudaGetSymbolAddress((void**)&cntE, g_cntE);
    cudaGetSymbolAddress((void**)&cntV, g_cntV);
    cudaGetSymbolAddress((void**)&curE, g_curE);
    cudaGetSymbolAddress((void**)&curV, g_curV);
    cudaGetSymbolAddress((void**)&rpE, g_rpE);
    cudaGetSymbolAddress((void**)&rpV, g_rpV);
    cudaGetSymbolAddress((void**)&colE, g_colE);
    cudaGetSymbolAddress((void**)&colV, g_colV);

    cudaFuncSetAttribute(k_gemm_tc, cudaFuncAttributeMaxDynamicSharedMemorySize,
                         GEMM_SMEM);

    const size_t ND = (size_t)NN * DIM;
    const size_t HD = (size_t)NH * DIM;

    // --- CSR build (both directions; once per call) ---
    k_init_min<<<1, 1>>>();
    k_min_reduce<<<256, 256>>>(dst, NE);
    k_zero4<<<32, 256>>>((float4*)cntE, NH / 4);
    k_zero4<<<64, 256>>>((float4*)cntV, NN / 4);
    k_zero4<<<32, 256>>>((float4*)curE, NH / 4);
    k_zero4<<<64, 256>>>((float4*)curV, NN / 4);
    k_cnt<<<(NE + 255) / 256, 256>>>(dst, cntE, NE, 1);
    k_cnt<<<(NE + 255) / 256, 256>>>(src, cntV, NE, 0);
    k_scan<<<1, 1024>>>(cntE, rpE, NH);
    k_scan<<<1, 1024>>>(cntV, rpV, NN);
    k_fill<<<(NE + 255) / 256, 256>>>(dst, rpE, curE, colE, NE, 1);
    k_fill<<<(NE + 255) / 256, 256>>>(src, rpV, curV, colV, NE, 0);

    // --- 2 layers of (V2E half-conv, E2V half-conv) ---
    for (int layer = 0; layer < 2; ++layer) {
        const float* inN = (layer == 0) ? x : n2;
        int m = 4 * layer;

        run_mlp(inN, n0, n1, P, m + 0, NN, true);                    // enc in n1
        k_gather<<<NH, 128>>>(n1, h0, rpE, colE, src, norm, 0);      // mean in h0
        run_mlp(h0, h1, h2, P, m + 1, NH, true);                     // x_he in h2

        run_mlp(h2, h0, h1, P, m + 2, NH, true);                     // enc in h1
        k_gather<<<NN, 128>>>(h1, n0, rpV, colV, dst, norm, 1);      // mean in n0
        run_mlp(n0, n1, n2, P, m + 3, NN, true);                     // x_node in n2
    }

    // --- heads ---
    const size_t DD = (size_t)DIM * DIM;
    float* oFinN  = out;
    float* oMeanN = out + ND;
    float* oStdN  = out + 2 * ND;
    float* oFinH  = out + 3 * ND;
    float* oMeanH = out + 3 * ND + HD;
    float* oStdH  = out + 3 * ND + 2 * HD;

    run_gemm(n2, eW1 + 0 * DD, eb1 + 0 * DIM, n0, NN, true);
    run_gemm(n0, eW2 + 0 * DD, eb2 + 0 * DIM, oMeanN, NN, false);
    run_gemm(n2, eW1 + 1 * DD, eb1 + 1 * DIM, n0, NN, true);
    run_gemm(n0, eW2 + 1 * DD, eb2 + 1 * DIM, n1, NN, false);
    k_mix<<<8192, 256>>>(n1, noiseN, oMeanN, oStdN, oFinN, ND);

    run_gemm(h2, eW1 + 2 * DD, eb1 + 2 * DIM, h0, NH, true);
    run_gemm(h0, eW2 + 2 * DD, eb2 + 2 * DIM, oMeanH, NH, false);
    run_gemm(h2, eW1 + 3 * DD, eb1 + 3 * DIM, h0, NH, true);
    run_gemm(h0, eW2 + 3 * DD, eb2 + 3 * DIM, h1, NH, false);
    k_mix<<<4096, 256>>>(h1, noiseH, oMeanH, oStdH, oFinH, HD);

    (void)in_sizes; (void)n_in; (void)out_size;
}

// round 13
// speedup vs baseline: 2.3761x; 1.0773x over previous
#include <cuda_runtime.h>
#include <cuda_bf16.h>
#include <math.h>
#include <stdint.h>

#define NN 50000
#define NH 10000
#define NE 250000
#define DIM 512
#define NSLOT 24

// ---------------------------------------------------------------------------
// Static scratch (no allocation allowed)
// ---------------------------------------------------------------------------
__device__ float g_n0[(size_t)NN * DIM];
__device__ float g_n1[(size_t)NN * DIM];
__device__ float g_n2[(size_t)NN * DIM];
__device__ float g_h0[(size_t)NH * DIM];
__device__ float g_h1[(size_t)NH * DIM];
__device__ float g_h2[(size_t)NH * DIM];
__device__ float2 g_stat[NN];
__device__ int   g_minv;
// packed split weights: [slot][kpair 0..255][n 0..511], word = bf16(k even)|bf16(k odd)<<16
__device__ uint32_t g_wph[(size_t)NSLOT * 256 * 512];
__device__ uint32_t g_wpl[(size_t)NSLOT * 256 * 512];
// CSR structures (rebuilt every call)
__device__ int g_cntE[NH], g_cntV[NN];
__device__ int g_curE[NH], g_curV[NN];
__device__ int g_rpE[NH + 1], g_rpV[NN + 1];
__device__ int g_colE[NE], g_colV[NE];

// ---------------------------------------------------------------------------
// Graph preprocessing
// ---------------------------------------------------------------------------
__global__ void k_init_min() { g_minv = 0x7fffffff; }

__global__ void k_min_reduce(const int* __restrict__ idx, int n) {
    int v = 0x7fffffff;
    for (int i = blockIdx.x * blockDim.x + threadIdx.x; i < n;
         i += gridDim.x * blockDim.x)
        v = min(v, __ldg(idx + i));
#pragma unroll
    for (int o = 16; o > 0; o >>= 1) v = min(v, __shfl_xor_sync(0xffffffffu, v, o));
    if ((threadIdx.x & 31) == 0) atomicMin(&g_minv, v);
}

__global__ void k_zero4(float4* __restrict__ p, size_t n4) {
    size_t i = (size_t)blockIdx.x * blockDim.x + threadIdx.x;
    size_t stride = (size_t)gridDim.x * blockDim.x;
    float4 z = make_float4(0.f, 0.f, 0.f, 0.f);
    for (; i < n4; i += stride) p[i] = z;
}

__global__ void k_cnt(const int* __restrict__ idx, int* __restrict__ cnt,
                      int n, int shift) {
    int i = blockIdx.x * blockDim.x + threadIdx.x;
    if (i < n) atomicAdd(&cnt[__ldg(idx + i) - (shift ? g_minv : 0)], 1);
}

__global__ __launch_bounds__(1024) void k_scan(const int* __restrict__ cnt,
                                               int* __restrict__ rp, int n) {
    __shared__ int part[1024];
    int t = threadIdx.x;
    int C = (n + 1023) >> 10;
    int base = t * C;
    int sum = 0;
    for (int i = 0; i < C; i++)
        if (base + i < n) sum += cnt[base + i];
    part[t] = sum;
    __syncthreads();
    for (int o = 1; o < 1024; o <<= 1) {
        int v = (t >= o) ? part[t - o] : 0;
        __syncthreads();
        part[t] += v;
        __syncthreads();
    }
    int excl = (t == 0) ? 0 : part[t - 1];
    for (int i = 0; i < C; i++)
        if (base + i < n) { rp[base + i] = excl; excl += cnt[base + i]; }
    if (t == 1023) rp[n] = part[1023];
}

__global__ void k_fill(const int* __restrict__ idx, const int* __restrict__ rp,
                       int* __restrict__ cur, int* __restrict__ col,
                       int n, int shift) {
    int i = blockIdx.x * blockDim.x + threadIdx.x;
    if (i < n) {
        int s = __ldg(idx + i) - (shift ? g_minv : 0);
        int p = atomicAdd(&cur[s], 1);
        col[rp[s] + p] = i;
    }
}

// ---------------------------------------------------------------------------
// Weight pre-split + pack: out[mat][kp][n] = bf16(W[2kp][n]) | bf16(W[2kp+1][n])<<16
// ---------------------------------------------------------------------------
__global__ void k_wsplit(const float* __restrict__ W, uint32_t* __restrict__ oh,
                         uint32_t* __restrict__ ol, int nmat) {
    int i = blockIdx.x * blockDim.x + threadIdx.x;
    int total = nmat * 256 * 512;
    if (i >= total) return;
    int mat = i >> 17;
    int rem = i & 131071;
    int kp = rem >> 9, n = rem & 511;
    const float* src = W + (size_t)mat * DIM * DIM;
    float a = __ldg(src + (size_t)(2 * kp) * DIM + n);
    float b = __ldg(src + (size_t)(2 * kp + 1) * DIM + n);
    __nv_bfloat16 ha = __float2bfloat16(a), hb = __float2bfloat16(b);
    oh[i] = (uint32_t)__bfloat16_as_ushort(ha) |
            ((uint32_t)__bfloat16_as_ushort(hb) << 16);
    ol[i] = (uint32_t)__bfloat16_as_ushort(__float2bfloat16(a - __bfloat162float(ha))) |
            ((uint32_t)__bfloat16_as_ushort(__float2bfloat16(b - __bfloat162float(hb))) << 16);
}

// ---------------------------------------------------------------------------
// LN row statistics: st[row] = (mu, rstd)
// ---------------------------------------------------------------------------
__global__ __launch_bounds__(256) void k_stat(const float* __restrict__ in,
                                              float2* __restrict__ st, int N) {
    int warp = threadIdx.x >> 5, lane = threadIdx.x & 31;
    int row = blockIdx.x * 8 + warp;
    if (row >= N) return;
    const float4* ip = reinterpret_cast<const float4*>(in + (size_t)row * DIM);
    float s = 0.f, ss = 0.f;
#pragma unroll
    for (int j = 0; j < 4; j++) {
        float4 v = ip[lane + 32 * j];
        s  += v.x + v.y + v.z + v.w;
        ss += v.x * v.x + v.y * v.y + v.z * v.z + v.w * v.w;
    }
#pragma unroll
    for (int o = 16; o > 0; o >>= 1) {
        s  += __shfl_xor_sync(0xffffffffu, s, o);
        ss += __shfl_xor_sync(0xffffffffu, ss, o);
    }
    if (lane == 0) {
        float mu = s * (1.f / DIM);
        st[row] = make_float2(mu, rsqrtf(ss * (1.f / DIM) - mu * mu + 1e-5f));
    }
}

// ---------------------------------------------------------------------------
// CSR segment-mean gather
// ---------------------------------------------------------------------------
__global__ __launch_bounds__(128) void k_gather(
    const float* __restrict__ feat, float* __restrict__ out,
    const int* __restrict__ rp, const int* __restrict__ col,
    const int* __restrict__ gidx, const float* __restrict__ norm, int gshift)
{
    int seg = blockIdx.x;
    int beg = rp[seg], end = rp[seg + 1];
    int t = threadIdx.x;
    int mv = g_minv;
    __shared__ int   se[128];
    __shared__ float sn[128];
    float4 acc = make_float4(0.f, 0.f, 0.f, 0.f);
    for (int base = beg; base < end; base += 128) {
        int nb = min(128, end - base);
        if (t < nb) {
            int e = __ldg(col + base + t);
            se[t] = __ldg(gidx + e) - (gshift ? mv : 0);
            sn[t] = __ldg(norm + e);
        }
        __syncthreads();
        for (int j = 0; j < nb; j++) {
            float4 v = *reinterpret_cast<const float4*>(
                feat + (size_t)se[j] * DIM + t * 4);
            float nv = sn[j];
            acc.x = fmaf(nv, v.x, acc.x);
            acc.y = fmaf(nv, v.y, acc.y);
            acc.z = fmaf(nv, v.z, acc.z);
            acc.w = fmaf(nv, v.w, acc.w);
        }
        __syncthreads();
    }
    float inv = 1.f / fmaxf((float)(end - beg), 1.f);
    acc.x *= inv; acc.y *= inv; acc.z *= inv; acc.w *= inv;
    *reinterpret_cast<float4*>(out + (size_t)seg * DIM + t * 4) = acc;
}

// ---------------------------------------------------------------------------
// Split-bf16 GEMM: double-buffered; W via cp.async of pre-packed tiles;
// A converted in loadRegs (overlapped) with optional fused LayerNorm.
// ---------------------------------------------------------------------------
#define ASTR 36
#define BSTR 136
#define A_WORDS (128 * ASTR)
#define SSTR (A_WORDS + 32 * BSTR)
#define GEMM_SMEM (2 * SSTR * 4)

__device__ __forceinline__ uint32_t pack_hi(float a, float b,
                                            uint32_t& lo) {
    __nv_bfloat16 ha = __float2bfloat16(a), hb = __float2bfloat16(b);
    lo = (uint32_t)__bfloat16_as_ushort(__float2bfloat16(a - __bfloat162float(ha))) |
         ((uint32_t)__bfloat16_as_ushort(__float2bfloat16(b - __bfloat162float(hb))) << 16);
    return (uint32_t)__bfloat16_as_ushort(ha) |
           ((uint32_t)__bfloat16_as_ushort(hb) << 16);
}

__device__ __forceinline__ void mma_bf16(float* c, const uint32_t* a,
                                         const uint32_t* b) {
    asm volatile(
        "mma.sync.aligned.m16n8k16.row.col.f32.bf16.bf16.f32 "
        "{%0,%1,%2,%3}, {%4,%5,%6,%7}, {%8,%9}, {%0,%1,%2,%3};"
        : "+f"(c[0]), "+f"(c[1]), "+f"(c[2]), "+f"(c[3])
        : "r"(a[0]), "r"(a[1]), "r"(a[2]), "r"(a[3]), "r"(b[0]), "r"(b[1]));
}

__device__ __forceinline__ void cp16(uint32_t d, const void* s) {
    asm volatile("cp.async.cg.shared.global [%0], [%1], 16;"
                 :: "r"(d), "l"(s) : "memory");
}

__device__ __forceinline__ uint32_t s2u(const void* p) {
    uint32_t r;
    asm("{ .reg .u64 t; cvta.to.shared.u64 t, %1; cvt.u32.u64 %0, t; }"
        : "=r"(r) : "l"(p));
    return r;
}

__global__ __launch_bounds__(256, 2) void k_gemm_tc(
    const float* __restrict__ A,
    const uint32_t* __restrict__ Wh, const uint32_t* __restrict__ Wl,
    const float* __restrict__ bias, float* __restrict__ C, int M, int relu,
    const float2* __restrict__ stat, const float* __restrict__ lnw,
    const float* __restrict__ lnb)
{
    extern __shared__ uint32_t sm[];
    const uint32_t smb = s2u(sm);

    const int t    = threadIdx.x;
    const int bm   = blockIdx.y * 128;
    const int bn   = blockIdx.x * 128;
    const int w    = t >> 5;
    const int lane = t & 31;
    const int g    = lane >> 2;
    const int tig  = lane & 3;
    const int m0   = (w & 1) * 64;
    const int n0   = (w >> 1) * 32;

    const int ar = t >> 3;
    const int ak = (t & 7) << 2;
    const int ap = (t & 7) << 1;

    float acc[4][4][4];
#pragma unroll
    for (int mf = 0; mf < 4; mf++)
#pragma unroll
        for (int nf = 0; nf < 4; nf++)
#pragma unroll
            for (int i = 0; i < 4; i++) acc[mf][nf][i] = 0.f;

    uint32_t uh[4][2], ul[4][2];

    // A tile: load + (optional LN affine) + split, all in registers
    auto loadRegs = [&](int i) {
        int kk = i * 32 + ak;
        float4 wv, bv;
        if (stat) {
            wv = __ldg(reinterpret_cast<const float4*>(lnw) + (kk >> 2));
            bv = __ldg(reinterpret_cast<const float4*>(lnb) + (kk >> 2));
        }
#pragma unroll
        for (int j = 0; j < 4; j++) {
            int r = bm + ar + 32 * j;
            float4 v = make_float4(0.f, 0.f, 0.f, 0.f);
            if (r < M)
                v = *reinterpret_cast<const float4*>(A + (size_t)r * DIM + kk);
            if (stat) {
                float2 s = __ldg(stat + min(r, M - 1));
                v.x = (v.x - s.x) * s.y * wv.x + bv.x;
                v.y = (v.y - s.x) * s.y * wv.y + bv.y;
                v.z = (v.z - s.x) * s.y * wv.z + bv.z;
                v.w = (v.w - s.x) * s.y * wv.w + bv.w;
            }
            uh[j][0] = pack_hi(v.x, v.y, ul[j][0]);
            uh[j][1] = pack_hi(v.z, v.w, ul[j][1]);
        }
    };
    auto storeA = [&](int s) {
        uint32_t* S = sm + s * SSTR;
#pragma unroll
        for (int j = 0; j < 4; j++) {
            uint32_t* d = S + (ar + 32 * j) * ASTR + ap;
            d[0]  = uh[j][0]; d[1]  = uh[j][1];
            d[16] = ul[j][0]; d[17] = ul[j][1];
        }
    };
    // B tile: cp.async of pre-packed words into [kp][n] stride-136 layout
    auto fillB = [&](int i, int s) {
        int kb = i * 16;
        uint32_t base = smb + (uint32_t)(s * SSTR + A_WORDS) * 4;
#pragma unroll
        for (int q = 0; q < 4; q++) {
            int c = t + 256 * q;
            int arr = c >> 9;            // 0=hi, 1=lo
            int cc = c & 511;
            int row = cc >> 5, col16 = cc & 31;
            const uint32_t* src = (arr ? Wl : Wh) +
                (size_t)(kb + row) * 512 + bn + col16 * 4;
            uint32_t dst = base + (uint32_t)(((arr ? row + 16 : row) * BSTR +
                                              col16 * 4) * 4);
            cp16(dst, src);
        }
        asm volatile("cp.async.commit_group;" ::: "memory");
    };

    // prologue
    fillB(0, 0);
    loadRegs(0);
    storeA(0);
    asm volatile("cp.async.wait_group 0;" ::: "memory");
    __syncthreads();
    loadRegs(1);

    for (int i = 0; i < 16; i++) {
        const int cur = i & 1;
        if (i < 15) { storeA(cur ^ 1); fillB(i + 1, cur ^ 1); }
        if (i < 14) loadRegs(i + 2);

        const uint32_t* SA = sm + cur * SSTR;
        const uint32_t* SB = SA + A_WORDS;
#pragma unroll
        for (int ks = 0; ks < 2; ks++) {
            const int kkp = ks * 8;
            uint32_t bh[4][2], bl[4][2];
#pragma unroll
            for (int nf = 0; nf < 4; nf++) {
                int bi = (kkp + tig) * BSTR + n0 + nf * 8 + g;
                bh[nf][0] = SB[bi];
                bh[nf][1] = SB[bi + 4 * BSTR];
                bl[nf][0] = SB[bi + 16 * BSTR];
                bl[nf][1] = SB[bi + 20 * BSTR];
            }
#pragma unroll
            for (int mf = 0; mf < 4; mf++) {
                int am = (m0 + mf * 16 + g) * ASTR + kkp + tig;
                uint32_t ah[4], al[4];
                ah[0] = SA[am];            ah[1] = SA[am + 8 * ASTR];
                ah[2] = SA[am + 4];        ah[3] = SA[am + 8 * ASTR + 4];
                al[0] = SA[am + 16];       al[1] = SA[am + 8 * ASTR + 16];
                al[2] = SA[am + 20];       al[3] = SA[am + 8 * ASTR + 20];
#pragma unroll
                for (int nf = 0; nf < 4; nf++) {
                    mma_bf16(acc[mf][nf], ah, bh[nf]);
                    mma_bf16(acc[mf][nf], ah, bl[nf]);
                    mma_bf16(acc[mf][nf], al, bh[nf]);
                }
            }
        }
        if (i < 15) {
            asm volatile("cp.async.wait_group 0;" ::: "memory");
            __syncthreads();
        }
    }

#pragma unroll
    for (int mf = 0; mf < 4; mf++) {
        int row0 = bm + m0 + mf * 16 + g;
#pragma unroll
        for (int nf = 0; nf < 4; nf++) {
            int col = bn + n0 + nf * 8 + tig * 2;
            float bv0 = __ldg(bias + col), bv1 = __ldg(bias + col + 1);
            float v0 = acc[mf][nf][0] + bv0, v1 = acc[mf][nf][1] + bv1;
            float v2 = acc[mf][nf][2] + bv0, v3 = acc[mf][nf][3] + bv1;
            if (relu) {
                v0 = fmaxf(v0, 0.f); v1 = fmaxf(v1, 0.f);
                v2 = fmaxf(v2, 0.f); v3 = fmaxf(v3, 0.f);
            }
            if (row0 < M)
                *reinterpret_cast<float2*>(C + (size_t)row0 * DIM + col) = make_float2(v0, v1);
            if (row0 + 8 < M)
                *reinterpret_cast<float2*>(C + (size_t)(row0 + 8) * DIM + col) = make_float2(v2, v3);
        }
    }
}

// ---------------------------------------------------------------------------
// Final heads epilogue
// ---------------------------------------------------------------------------
__global__ void k_mix(const float* __restrict__ pre, const float* __restrict__ noise,
                      const float* __restrict__ mean, float* __restrict__ ostd,
                      float* __restrict__ ofin, size_t n)
{
    size_t i = (size_t)blockIdx.x * blockDim.x + threadIdx.x;
    size_t stride = (size_t)gridDim.x * blockDim.x;
    for (; i < n; i += stride) {
        float x = pre[i];
        float sp = fmaxf(x, 0.f) + log1pf(expf(-fabsf(x)));
        ostd[i] = sp;
        ofin[i] = fmaf(noise[i], sp, mean[i]);
    }
}

// ---------------------------------------------------------------------------
// Host orchestration
// ---------------------------------------------------------------------------
static uint32_t *d_wph, *d_wpl;
static float2 *d_stat;

static void run_gemm(const float* A, int slot, const float* bias, float* C,
                     int M, bool relu, bool ln, const float* lnw,
                     const float* lnb) {
    dim3 grid(DIM / 128, (M + 127) / 128);
    k_gemm_tc<<<grid, 256, GEMM_SMEM>>>(
        A, d_wph + (size_t)slot * 256 * 512, d_wpl + (size_t)slot * 256 * 512,
        bias, C, M, relu ? 1 : 0, ln ? d_stat : nullptr, lnw, lnb);
}

struct MlpParams {
    const float *ln0w, *ln0b, *b1, *ln1w, *ln1b, *b2;
};

static void run_mlp(const float* in, float* t2, const MlpParams& P,
                    int k, int N, bool relu_out) {
    k_stat<<<(N + 7) / 8, 256>>>(in, d_stat, N);
    run_gemm(in, k, P.b1 + (size_t)k * DIM, t2, N, true, true,
             P.ln0w + (size_t)k * DIM, P.ln0b + (size_t)k * DIM);
    k_stat<<<(N + 7) / 8, 256>>>(t2, d_stat, N);
    run_gemm(t2, 8 + k, P.b2 + (size_t)k * DIM, t2, N, relu_out, true,
             P.ln1w + (size_t)k * DIM, P.ln1b + (size_t)k * DIM);
}

extern "C" void kernel_launch(void* const* d_in, const int* in_sizes, int n_in,
                              void* d_out, int out_size) {
    const float* x    = (const float*)d_in[0];
    const int*   eidx = (const int*)  d_in[1];
    const float* norm = (const float*)d_in[2];
    MlpParams P;
    P.ln0w = (const float*)d_in[3];
    P.ln0b = (const float*)d_in[4];
    const float* mlpW1 = (const float*)d_in[5];
    P.b1   = (const float*)d_in[6];
    P.ln1w = (const float*)d_in[7];
    P.ln1b = (const float*)d_in[8];
    const float* mlpW2 = (const float*)d_in[9];
    P.b2   = (const float*)d_in[10];
    const float* eW1    = (const float*)d_in[11];
    const float* eb1    = (const float*)d_in[12];
    const float* eW2    = (const float*)d_in[13];
    const float* eb2    = (const float*)d_in[14];
    const float* noiseN = (const float*)d_in[15];
    const float* noiseH = (const float*)d_in[16];
    float* out = (float*)d_out;

    const int* src = eidx;
    const int* dst = eidx + NE;

    float *n0, *n1, *n2, *h0, *h1, *h2;
    int *cntE, *cntV, *curE, *curV, *rpE, *rpV, *colE, *colV;
    cudaGetSymbolAddress((void**)&n0, g_n0);
    cudaGetSymbolAddress((void**)&n1, g_n1);
    cudaGetSymbolAddress((void**)&n2, g_n2);
    cudaGetSymbolAddress((void**)&h0, g_h0);
    cudaGetSymbolAddress((void**)&h1, g_h1);
    cudaGetSymbolAddress((void**)&h2, g_h2);
    cudaGetSymbolAddress((void**)&cntE, g_cntE);
    cudaGetSymbolAddress((void**)&cntV, g_cntV);
    cudaGetSymbolAddress((void**)&curE, g_curE);
    cudaGetSymbolAddress((void**)&curV, g_curV);
    cudaGetSymbolAddress((void**)&rpE, g_rpE);
    cudaGetSymbolAddress((void**)&rpV, g_rpV);
    cudaGetSymbolAddress((void**)&colE, g_colE);
    cudaGetSymbolAddress((void**)&colV, g_colV);
    cudaGetSymbolAddress((void**)&d_wph, g_wph);
    cudaGetSymbolAddress((void**)&d_wpl, g_wpl);
    cudaGetSymbolAddress((void**)&d_stat, g_stat);

    cudaFuncSetAttribute(k_gemm_tc, cudaFuncAttributeMaxDynamicSharedMemorySize,
                         GEMM_SMEM);

    const size_t ND = (size_t)NN * DIM;
    const size_t HD = (size_t)NH * DIM;
    const size_t WSL = (size_t)256 * 512;

    // --- weight pre-split/pack: slots 0-7 W1, 8-15 W2, 16-19 eW1, 20-23 eW2 ---
    {
        int tot8 = 8 * 256 * 512, tot4 = 4 * 256 * 512;
        k_wsplit<<<(tot8 + 255) / 256, 256>>>(mlpW1, d_wph, d_wpl, 8);
        k_wsplit<<<(tot8 + 255) / 256, 256>>>(mlpW2, d_wph + 8 * WSL, d_wpl + 8 * WSL, 8);
        k_wsplit<<<(tot4 + 255) / 256, 256>>>(eW1, d_wph + 16 * WSL, d_wpl + 16 * WSL, 4);
        k_wsplit<<<(tot4 + 255) / 256, 256>>>(eW2, d_wph + 20 * WSL, d_wpl + 20 * WSL, 4);
    }

    // --- CSR build ---
    k_init_min<<<1, 1>>>();
    k_min_reduce<<<256, 256>>>(dst, NE);
    k_zero4<<<32, 256>>>((float4*)cntE, NH / 4);
    k_zero4<<<64, 256>>>((float4*)cntV, NN / 4);
    k_zero4<<<32, 256>>>((float4*)curE, NH / 4);
    k_zero4<<<64, 256>>>((float4*)curV, NN / 4);
    k_cnt<<<(NE + 255) / 256, 256>>>(dst, cntE, NE, 1);
    k_cnt<<<(NE + 255) / 256, 256>>>(src, cntV, NE, 0);
    k_scan<<<1, 1024>>>(cntE, rpE, NH);
    k_scan<<<1, 1024>>>(cntV, rpV, NN);
    k_fill<<<(NE + 255) / 256, 256>>>(dst, rpE, curE, colE, NE, 1);
    k_fill<<<(NE + 255) / 256, 256>>>(src, rpV, curV, colV, NE, 0);

    // --- 2 layers ---
    for (int layer = 0; layer < 2; ++layer) {
        const float* inN = (layer == 0) ? x : n2;
        int m = 4 * layer;

        run_mlp(inN, n1, P, m + 0, NN, true);                    // enc in n1
        k_gather<<<NH, 128>>>(n1, h0, rpE, colE, src, norm, 0);  // mean in h0
        run_mlp(h0, h2, P, m + 1, NH, true);                     // x_he in h2

        run_mlp(h2, h1, P, m + 2, NH, true);                     // enc in h1
        k_gather<<<NN, 128>>>(h1, n0, rpV, colV, dst, norm, 1);  // mean in n0
        run_mlp(n0, n2, P, m + 3, NN, true);                     // x_node in n2
    }

    // --- heads (no LN) ---
    float* oFinN  = out;
    float* oMeanN = out + ND;
    float* oStdN  = out + 2 * ND;
    float* oFinH  = out + 3 * ND;
    float* oMeanH = out + 3 * ND + HD;
    float* oStdH  = out + 3 * ND + 2 * HD;

    run_gemm(n2, 16, eb1 + 0 * DIM, n0, NN, true, false, nullptr, nullptr);
    run_gemm(n0, 20, eb2 + 0 * DIM, oMeanN, NN, false, false, nullptr, nullptr);
    run_gemm(n2, 17, eb1 + 1 * DIM, n0, NN, true, false, nullptr, nullptr);
    run_gemm(n0, 21, eb2 + 1 * DIM, n1, NN, false, false, nullptr, nullptr);
    k_mix<<<8192, 256>>>(n1, noiseN, oMeanN, oStdN, oFinN, ND);

    run_gemm(h2, 18, eb1 + 2 * DIM, h0, NH, true, false, nullptr, nullptr);
    run_gemm(h0, 22, eb2 + 2 * DIM, oMeanH, NH, false, false, nullptr, nullptr);
    run_gemm(h2, 19, eb1 + 3 * DIM, h0, NH, true, false, nullptr, nullptr);
    run_gemm(h0, 23, eb2 + 3 * DIM, h1, NH, false, false, nullptr, nullptr);
    k_mix<<<4096, 256>>>(h1, noiseH, oMeanH, oStdH, oFinH, HD);

    (void)in_sizes; (void)n_in; (void)out_size;
}